// round 7
// baseline (speedup 1.0000x reference)
#include <cuda_runtime.h>
#include <cstdint>

typedef unsigned long long ull;

#define B_SZ  16384
#define V_DIM 20
#define F_DIM 15
#define H_DIM 256

// ---------------------------------------------------------------------------
// f32x2 packed math (Blackwell: fma.rn.f32x2 doubles fp32 FMA throughput)
// ---------------------------------------------------------------------------
__device__ __forceinline__ ull pk2(float a) {
    ull r; asm("mov.b64 %0, {%1, %1};" : "=l"(r) : "f"(a)); return r;
}
__device__ __forceinline__ ull pk(float a, float b) {
    ull r; asm("mov.b64 %0, {%1, %2};" : "=l"(r) : "f"(a), "f"(b)); return r;
}
__device__ __forceinline__ void ffma2(ull &d, ull a, ull b) {
    asm("fma.rn.f32x2 %0, %1, %2, %0;" : "+l"(d) : "l"(a), "l"(b));
}
__device__ __forceinline__ float2 upk(ull v) {
    float2 f; asm("mov.b64 {%0, %1}, %2;" : "=f"(f.x), "=f"(f.y) : "l"(v)); return f;
}
__device__ __forceinline__ float sigm(float x) {
    return __fdividef(1.0f, 1.0f + __expf(-x));
}

// ---------------------------------------------------------------------------
// Device-global scratch (sanctioned alloc-free scratch)
// ---------------------------------------------------------------------------
__device__ float g_WhhT[256 * 768];          // [k][768]   = W_hh^T
__device__ float g_WihT[16 * 768];           // [k<=15][768] = W_ih^T, row 15 = 0
__device__ float g_W1t[272 * 1024];          // [k][n], row 271 = 0
__device__ float g_W2t[1024 * 1024];
__device__ float g_W3t[1024 * 512];
__device__ float g_W4t[512 * 256];
__device__ float g_xcat[(size_t)B_SZ * 272]; // [b][0:15 feat | 15:271 h | 271 pad]
__device__ float g_actA[(size_t)B_SZ * 1024];
__device__ float g_actB[(size_t)B_SZ * 1024];

// ---------------------------------------------------------------------------
// Prep: out[Kp][N] = in[N][K]^T with zero row padding
// ---------------------------------------------------------------------------
__global__ void transpose_pad(const float* __restrict__ in, float* __restrict__ out,
                              int N, int K, int Kp)
{
    int idx = blockIdx.x * 256 + threadIdx.x;
    int total = Kp * N;
    if (idx >= total) return;
    int k = idx / N, n = idx - k * N;
    out[idx] = (k < K) ? in[n * K + k] : 0.0f;
}

// ---------------------------------------------------------------------------
// GRU kernel: 32 batch rows / CTA, 512 threads, h resident in SMEM 20 steps.
// Per step: 3 gate chunks (r,z,n) of GEMM [32 x 256] = h[32x256] @ WhhT chunk,
// each chunk = 16 h-tiles + 1 x-tile (x * W_ih fused, zero-padded K=16).
// Weight tiles double-buffered in SMEM (1 barrier per tile).
// Thread (warp w, lane tx): rows {2w, 2w+1}, cols [8*tx, 8*tx+8).
// ---------------------------------------------------------------------------
#define GRU_SMEM_BYTES (17920 * 4)   // Wbuf 8192 | h 8192 | x 512 | bias 1024

#define INITB(A_, OFF_) { \
    const ulonglong2* bb = (const ulonglong2*)(bi_s + (OFF_) + c0); \
    ulonglong2 bA = bb[0], bB = bb[1]; \
    A_[0][0]=bA.x; A_[0][1]=bA.y; A_[0][2]=bB.x; A_[0][3]=bB.y; \
    A_[1][0]=bA.x; A_[1][1]=bA.y; A_[1][2]=bB.x; A_[1][3]=bB.y; }

#define COMP16(A_, BASE_, STRIDE_, KB_) { \
    const float* ap0 = (BASE_) + r0 * (STRIDE_) + (KB_); \
    const float* ap1 = (BASE_) + r1 * (STRIDE_) + (KB_); \
    const float* wp  = Wb + buf * 4096 + c0; \
    _Pragma("unroll") \
    for (int k = 0; k < 16; ++k) { \
        ull pa0 = pk2(ap0[k]); \
        ull pa1 = pk2(ap1[k]); \
        ulonglong2 bA = *(const ulonglong2*)(wp + k * 256); \
        ulonglong2 bB = *(const ulonglong2*)(wp + k * 256 + 4); \
        ffma2(A_[0][0], pa0, bA.x); ffma2(A_[0][1], pa0, bA.y); \
        ffma2(A_[0][2], pa0, bB.x); ffma2(A_[0][3], pa0, bB.y); \
        ffma2(A_[1][0], pa1, bA.x); ffma2(A_[1][1], pa1, bA.y); \
        ffma2(A_[1][2], pa1, bB.x); ffma2(A_[1][3], pa1, bB.y); \
    } }

#define TILE_ADV() { __syncthreads(); buf ^= 1; nxt = (nxt == 50) ? 0 : nxt + 1; }

__global__ __launch_bounds__(512, 1)
void gru_kernel(const float* __restrict__ state,
                const float* __restrict__ b_ih,
                const float* __restrict__ b_hh)
{
    extern __shared__ __align__(16) float dsm[];
    float* Wb   = dsm;            // [2][16*256]
    float* h_s  = dsm + 8192;     // [32][256]
    float* x_s  = dsm + 16384;    // [32][16]
    float* bi_s = dsm + 16896;    // [4][256]: r-sum | z-sum | bhh_n | bih_n

    const int tid = threadIdx.x;
    const int wrp = tid >> 5;
    const int tx  = tid & 31;
    const int r0  = wrp * 2, r1 = r0 + 1;
    const int c0  = tx * 8;
    const int b0  = blockIdx.x * 32;

    for (int i = tid; i < 8192; i += 512) h_s[i] = 0.0f;
    if (tid < 512) x_s[tid] = 0.0f;
    if (tid < 256) {
        bi_s[tid]       = b_ih[tid]       + b_hh[tid];
        bi_s[256 + tid] = b_ih[256 + tid] + b_hh[256 + tid];
        bi_s[512 + tid] = b_hh[512 + tid];
        bi_s[768 + tid] = b_ih[512 + tid];
    }

    // weight-tile staging: thread covers 8 consecutive floats of the 16x256 tile
    const int f0  = tid * 8;
    const int skk = f0 >> 8;     // tile row 0..15
    const int scc = f0 & 255;    // tile col (mult of 8)

    auto stage = [&](int T, int dstb) {
        int g  = T / 17;
        int kt = T - g * 17;
        const float* src = (kt < 16)
            ? (g_WhhT + (size_t)(kt * 16 + skk) * 768 + g * 256 + scc)
            : (g_WihT + (size_t)skk * 768 + g * 256 + scc);
        float4 v0 = *(const float4*)src;
        float4 v1 = *(const float4*)(src + 4);
        float* d = Wb + dstb * 4096 + skk * 256 + scc;
        *(float4*)d       = v0;
        *(float4*)(d + 4) = v1;
    };

    stage(0, 0);
    __syncthreads();

    int buf = 0, nxt = 1;
    ull acc[2][4], xacc[2][4], rv[2][4], zv[2][4];

    for (int t = 0; t < V_DIM; ++t) {
        // stage x features for this step
        if (tid < 480) {
            int row = tid / 15, f = tid - row * 15;
            x_s[row * 16 + f] = state[((size_t)(b0 + row) * V_DIM + t) * F_DIM + f];
        }
        __syncthreads();

        // ---- chunk r ----
        INITB(acc, 0);
        for (int kt = 0; kt < 16; ++kt) {
            stage(nxt, buf ^ 1);
            COMP16(acc, h_s, 256, kt * 16);
            TILE_ADV();
        }
        stage(nxt, buf ^ 1);
        COMP16(acc, x_s, 16, 0);
        TILE_ADV();
        #pragma unroll
        for (int i = 0; i < 2; ++i)
            #pragma unroll
            for (int j = 0; j < 4; ++j) {
                float2 v = upk(acc[i][j]);
                rv[i][j] = pk(sigm(v.x), sigm(v.y));
            }

        // ---- chunk z ----
        INITB(acc, 256);
        for (int kt = 0; kt < 16; ++kt) {
            stage(nxt, buf ^ 1);
            COMP16(acc, h_s, 256, kt * 16);
            TILE_ADV();
        }
        stage(nxt, buf ^ 1);
        COMP16(acc, x_s, 16, 0);
        TILE_ADV();
        #pragma unroll
        for (int i = 0; i < 2; ++i)
            #pragma unroll
            for (int j = 0; j < 4; ++j) {
                float2 v = upk(acc[i][j]);
                zv[i][j] = pk(sigm(v.x), sigm(v.y));
            }

        // ---- chunk n (h-part -> acc with bhh_n; x-part -> xacc with bih_n) ----
        INITB(acc, 512);
        for (int kt = 0; kt < 16; ++kt) {
            stage(nxt, buf ^ 1);
            COMP16(acc, h_s, 256, kt * 16);
            TILE_ADV();
        }
        INITB(xacc, 768);
        stage(nxt, buf ^ 1);
        COMP16(xacc, x_s, 16, 0);
        TILE_ADV();

        // ---- epilogue: n = tanh(xn + r*hn); h = n + z*(h - n) ----
        #pragma unroll
        for (int i = 0; i < 2; ++i) {
            float* hp = h_s + (r0 + i) * 256 + c0;
            #pragma unroll
            for (int j = 0; j < 4; ++j) {
                float2 hn = upk(acc[i][j]);
                float2 xn = upk(xacc[i][j]);
                float2 rr = upk(rv[i][j]);
                float2 zz = upk(zv[i][j]);
                float n0 = tanhf(xn.x + rr.x * hn.x);
                float n1 = tanhf(xn.y + rr.y * hn.y);
                float h0 = hp[2 * j], h1 = hp[2 * j + 1];
                hp[2 * j]     = n0 + zz.x * (h0 - n0);
                hp[2 * j + 1] = n1 + zz.y * (h1 - n1);
            }
        }
        __syncthreads();
    }

    // write xcat = [feat(15) | h(256) | pad(1)]
    #pragma unroll
    for (int i = 0; i < 2; ++i) {
        int rr = r0 + i;
        const float* hp = h_s + rr * 256 + c0;
        float* dst = g_xcat + (size_t)(b0 + rr) * 272 + 15 + c0;
        #pragma unroll
        for (int c = 0; c < 8; ++c) dst[c] = hp[c];
    }
    if (tid < 480) {
        int row = tid / 15, f = tid - row * 15;
        g_xcat[(size_t)(b0 + row) * 272 + f] =
            state[((size_t)(b0 + row) * V_DIM) * F_DIM + f];
    }
    if (tid < 32) g_xcat[(size_t)(b0 + tid) * 272 + 271] = 0.0f;
}

// ---------------------------------------------------------------------------
// MLP GEMM: C[M][N] = relu(A[M][K] @ Wt[K][N] + bias), 128x128 tile, BK=16,
// 256 threads, 8x8 per thread, f32x2 inner, double-buffered SMEM.
// ---------------------------------------------------------------------------
__global__ __launch_bounds__(256, 2)
void mlp_gemm(const float* __restrict__ A, const float* __restrict__ Wt,
              const float* __restrict__ bias, float* __restrict__ C,
              int K, int N)
{
    __shared__ __align__(16) float A_s[2][16 * 128];
    __shared__ __align__(16) float W_s[2][16 * 128];

    const int tid  = threadIdx.x;
    const int tx   = tid & 15, ty = tid >> 4;
    const int m0   = blockIdx.y << 7, n0 = blockIdx.x << 7;
    const int crow = ty * 8, ccol = tx * 8;

    ull acc[8][4];
    #pragma unroll
    for (int j = 0; j < 8; ++j)
        #pragma unroll
        for (int c = 0; c < 4; ++c) acc[j][c] = 0ull;

    const int ar = tid >> 1;          // A stage: row 0..127
    const int ac = (tid & 1) * 8;     // A stage: k sub-offset 0 or 8
    const int wk = ty;                // W stage: tile row
    const int wc = ccol;              // W stage: col (mult of 8)

    // prologue stage k0 = 0
    {
        const float* sa = A + (size_t)(m0 + ar) * K + ac;
        float4 a0 = *(const float4*)sa, a1 = *(const float4*)(sa + 4);
        A_s[0][(ac+0)*128+ar]=a0.x; A_s[0][(ac+1)*128+ar]=a0.y;
        A_s[0][(ac+2)*128+ar]=a0.z; A_s[0][(ac+3)*128+ar]=a0.w;
        A_s[0][(ac+4)*128+ar]=a1.x; A_s[0][(ac+5)*128+ar]=a1.y;
        A_s[0][(ac+6)*128+ar]=a1.z; A_s[0][(ac+7)*128+ar]=a1.w;
        const float* sw = Wt + (size_t)wk * N + n0 + wc;
        *(float4*)&W_s[0][wk*128+wc]   = *(const float4*)sw;
        *(float4*)&W_s[0][wk*128+wc+4] = *(const float4*)(sw + 4);
    }
    __syncthreads();

    const int ntile = K >> 4;
    for (int tk = 0; tk < ntile; ++tk) {
        const int cb = tk & 1;
        if (tk + 1 < ntile) {
            const int nb = cb ^ 1, k0 = (tk + 1) << 4;
            const float* sa = A + (size_t)(m0 + ar) * K + k0 + ac;
            float4 a0 = *(const float4*)sa, a1 = *(const float4*)(sa + 4);
            A_s[nb][(ac+0)*128+ar]=a0.x; A_s[nb][(ac+1)*128+ar]=a0.y;
            A_s[nb][(ac+2)*128+ar]=a0.z; A_s[nb][(ac+3)*128+ar]=a0.w;
            A_s[nb][(ac+4)*128+ar]=a1.x; A_s[nb][(ac+5)*128+ar]=a1.y;
            A_s[nb][(ac+6)*128+ar]=a1.z; A_s[nb][(ac+7)*128+ar]=a1.w;
            const float* sw = Wt + (size_t)(k0 + wk) * N + n0 + wc;
            *(float4*)&W_s[nb][wk*128+wc]   = *(const float4*)sw;
            *(float4*)&W_s[nb][wk*128+wc+4] = *(const float4*)(sw + 4);
        }
        #pragma unroll
        for (int k = 0; k < 16; ++k) {
            float4 a0 = *(const float4*)&A_s[cb][k * 128 + crow];
            float4 a1 = *(const float4*)&A_s[cb][k * 128 + crow + 4];
            ulonglong2 bA = *(const ulonglong2*)&W_s[cb][k * 128 + ccol];
            ulonglong2 bB = *(const ulonglong2*)&W_s[cb][k * 128 + ccol + 4];
            float av[8] = {a0.x, a0.y, a0.z, a0.w, a1.x, a1.y, a1.z, a1.w};
            #pragma unroll
            for (int j = 0; j < 8; ++j) {
                ull pa = pk2(av[j]);
                ffma2(acc[j][0], pa, bA.x);
                ffma2(acc[j][1], pa, bA.y);
                ffma2(acc[j][2], pa, bB.x);
                ffma2(acc[j][3], pa, bB.y);
            }
        }
        __syncthreads();
    }

    float bvf[8];
    *(float4*)&bvf[0] = *(const float4*)(bias + n0 + ccol);
    *(float4*)&bvf[4] = *(const float4*)(bias + n0 + ccol + 4);
    #pragma unroll
    for (int j = 0; j < 8; ++j) {
        float o[8];
        #pragma unroll
        for (int c = 0; c < 4; ++c) {
            float2 v = upk(acc[j][c]);
            o[2*c]   = fmaxf(v.x + bvf[2*c],   0.0f);
            o[2*c+1] = fmaxf(v.y + bvf[2*c+1], 0.0f);
        }
        float* dst = C + (size_t)(m0 + crow + j) * N + n0 + ccol;
        *(float4*)dst       = make_float4(o[0], o[1], o[2], o[3]);
        *(float4*)(dst + 4) = make_float4(o[4], o[5], o[6], o[7]);
    }
}

// ---------------------------------------------------------------------------
// Head: out[b] = tanh(dot(a4[b], Wp) + bp)  -- one warp per row
// ---------------------------------------------------------------------------
__global__ void head_kernel(const float* __restrict__ A, const float* __restrict__ Wp,
                            const float* __restrict__ bp, float* __restrict__ out)
{
    __shared__ float wsh[256];
    int tid = threadIdx.x;
    wsh[tid] = Wp[tid];
    __syncthreads();
    int warp = tid >> 5, lane = tid & 31;
    int b = blockIdx.x * 8 + warp;
    const float* a = A + (size_t)b * 256;
    float s = 0.0f;
    #pragma unroll
    for (int i = 0; i < 8; ++i) s += a[lane + 32 * i] * wsh[lane + 32 * i];
    #pragma unroll
    for (int o = 16; o; o >>= 1) s += __shfl_xor_sync(0xffffffffu, s, o);
    if (lane == 0) out[b] = tanhf(s + bp[0]);
}

// ---------------------------------------------------------------------------
// Launch
// ---------------------------------------------------------------------------
extern "C" void kernel_launch(void* const* d_in, const int* in_sizes, int n_in,
                              void* d_out, int out_size)
{
    const float* state = (const float*)d_in[0];
    const float* W_ih  = (const float*)d_in[1];
    const float* W_hh  = (const float*)d_in[2];
    const float* b_ih  = (const float*)d_in[3];
    const float* b_hh  = (const float*)d_in[4];
    const float* W1 = (const float*)d_in[5];  const float* b1 = (const float*)d_in[6];
    const float* W2 = (const float*)d_in[7];  const float* b2 = (const float*)d_in[8];
    const float* W3 = (const float*)d_in[9];  const float* b3 = (const float*)d_in[10];
    const float* W4 = (const float*)d_in[11]; const float* b4 = (const float*)d_in[12];
    const float* Wp = (const float*)d_in[13]; const float* bp = (const float*)d_in[14];
    float* out = (float*)d_out;

    float *pWhhT, *pWihT, *pW1t, *pW2t, *pW3t, *pW4t, *pXcat, *pA, *pB;
    cudaGetSymbolAddress((void**)&pWhhT, g_WhhT);
    cudaGetSymbolAddress((void**)&pWihT, g_WihT);
    cudaGetSymbolAddress((void**)&pW1t,  g_W1t);
    cudaGetSymbolAddress((void**)&pW2t,  g_W2t);
    cudaGetSymbolAddress((void**)&pW3t,  g_W3t);
    cudaGetSymbolAddress((void**)&pW4t,  g_W4t);
    cudaGetSymbolAddress((void**)&pXcat, g_xcat);
    cudaGetSymbolAddress((void**)&pA,    g_actA);
    cudaGetSymbolAddress((void**)&pB,    g_actB);

    cudaFuncSetAttribute(gru_kernel, cudaFuncAttributeMaxDynamicSharedMemorySize,
                         GRU_SMEM_BYTES);

    // prep: weight transposes (cheap; L2-resident thereafter)
    transpose_pad<<<(256 * 768   + 255) / 256, 256>>>(W_hh, pWhhT, 768, 256, 256);
    transpose_pad<<<(16 * 768    + 255) / 256, 256>>>(W_ih, pWihT, 768, 15, 16);
    transpose_pad<<<(272 * 1024  + 255) / 256, 256>>>(W1, pW1t, 1024, 271, 272);
    transpose_pad<<<(1024 * 1024 + 255) / 256, 256>>>(W2, pW2t, 1024, 1024, 1024);
    transpose_pad<<<(1024 * 512  + 255) / 256, 256>>>(W3, pW3t, 512, 1024, 1024);
    transpose_pad<<<(512 * 256   + 255) / 256, 256>>>(W4, pW4t, 256, 512, 512);

    // GRU over V=20, produces g_xcat [B][272]
    gru_kernel<<<B_SZ / 32, 512, GRU_SMEM_BYTES>>>(state, b_ih, b_hh);

    // MLP
    mlp_gemm<<<dim3(8, 128), 256>>>(pXcat, pW1t, b1, pA, 272, 1024);
    mlp_gemm<<<dim3(8, 128), 256>>>(pA,    pW2t, b2, pB, 1024, 1024);
    mlp_gemm<<<dim3(4, 128), 256>>>(pB,    pW3t, b3, pA, 1024, 512);
    mlp_gemm<<<dim3(2, 128), 256>>>(pA,    pW4t, b4, pB, 512, 256);

    // head
    head_kernel<<<B_SZ / 8, 256>>>(pB, Wp, bp, out);
}

// round 9
// speedup vs baseline: 2.6388x; 2.6388x over previous
#include <cuda_runtime.h>
#include <cstdint>

typedef unsigned long long ull;

#define B_SZ  16384
#define V_DIM 20
#define F_DIM 15

// ---------------------------------------------------------------------------
// f32x2 packed math helpers
// ---------------------------------------------------------------------------
__device__ __forceinline__ ull pk2(float a) {
    ull r; asm("mov.b64 %0, {%1, %1};" : "=l"(r) : "f"(a)); return r;
}
__device__ __forceinline__ void ffma2(ull &d, ull a, ull b) {
    asm("fma.rn.f32x2 %0, %1, %2, %0;" : "+l"(d) : "l"(a), "l"(b));
}
__device__ __forceinline__ float2 upk(ull v) {
    float2 f; asm("mov.b64 {%0, %1}, %2;" : "=f"(f.x), "=f"(f.y) : "l"(v)); return f;
}
__device__ __forceinline__ float sigm(float x) {
    return __fdividef(1.0f, 1.0f + __expf(-x));
}
__device__ __forceinline__ float tanhfast(float x) {
    float y; asm("tanh.approx.f32 %0, %1;" : "=f"(y) : "f"(x)); return y;
}

// ---------------------------------------------------------------------------
// Device-global scratch
// ---------------------------------------------------------------------------
__device__ float g_WhhT[256 * 768];                      // [k][768] = W_hh^T
__device__ float g_WihT[16 * 768];                       // [k][768] = W_ih^T (k=15 zero)
__device__ float g_W1t[272 * 1024];                      // permuted: [h|feat|pad] x n
__device__ float g_W2t[1024 * 1024];
__device__ float g_W3t[1024 * 512];
__device__ float g_W4t[512 * 256];
__device__ float g_state16[(size_t)B_SZ * V_DIM * 16];   // state padded K=16
__device__ float g_xg[(size_t)B_SZ * V_DIM * 768];       // precomputed input gates
__device__ float g_xcat[(size_t)B_SZ * 272];             // [h(256)|feat(15)|pad]
__device__ float g_actA[(size_t)B_SZ * 1024];
__device__ float g_actB[(size_t)B_SZ * 1024];

// ---------------------------------------------------------------------------
// Prep kernels
// ---------------------------------------------------------------------------
__global__ void transpose_pad(const float* __restrict__ in, float* __restrict__ out,
                              int N, int K, int Kp)
{
    int idx = blockIdx.x * 256 + threadIdx.x;
    int total = Kp * N;
    if (idx >= total) return;
    int k = idx / N, n = idx - k * N;
    out[idx] = (k < K) ? in[n * K + k] : 0.0f;
}

// W1 transposed with column permutation matching xcat = [h(256)|feat(15)|pad]
__global__ void transpose_w1(const float* __restrict__ W1, float* __restrict__ out)
{
    int idx = blockIdx.x * 256 + threadIdx.x;
    if (idx >= 272 * 1024) return;
    int k = idx >> 10, n = idx & 1023;
    float v = 0.0f;
    if (k < 256)      v = W1[n * 271 + 15 + k];    // h part
    else if (k < 271) v = W1[n * 271 + (k - 256)]; // feature part
    out[idx] = v;
}

__global__ void pad_state16(const float* __restrict__ s, float* __restrict__ o)
{
    int idx = blockIdx.x * 256 + threadIdx.x;
    if (idx >= B_SZ * V_DIM * 16) return;
    int r = idx >> 4, c = idx & 15;
    o[idx] = (c < F_DIM) ? s[r * F_DIM + c] : 0.0f;
}

// ---------------------------------------------------------------------------
// GRU kernel. CTA = 32 batch rows, 256 threads (8 warps).
// Thread: 8 rows x 4 cols x 3 gates, all gates fused per K-pass (K=256).
// h transposed in SMEM [k][36-padded rows] -> broadcast A loads.
// W tiles [16][768] double-buffered; LDS lane-stride 16B conflict-free.
// xg (input-side gates + b_ih) precomputed, loaded in epilogue.
// ---------------------------------------------------------------------------
#define ASTRIDE 36
#define GRU_SMEM_FLOATS (2 * 16 * 768 + 256 * ASTRIDE + 768)
#define GRU_SMEM_BYTES  (GRU_SMEM_FLOATS * 4)

__global__ __launch_bounds__(256, 1)
void gru_kernel(const float* __restrict__ state, const float* __restrict__ b_hh)
{
    extern __shared__ __align__(16) float sm[];
    float* W_s = sm;                       // [2][16*768]
    float* A_s = sm + 2 * 16 * 768;        // [256][ASTRIDE]
    float* bb  = A_s + 256 * ASTRIDE;      // [768] = b_hh

    const int tid  = threadIdx.x;
    const int w    = tid >> 5, lane = tid & 31;
    const int cg   = w & 1, rg = w >> 1;        // col-group, row-group
    const int r0   = rg * 8;
    const int hcol = cg * 128 + lane * 4;       // 4 cols within 256
    const int b0   = blockIdx.x * 32;

    for (int i = tid; i < 256 * ASTRIDE; i += 256) A_s[i] = 0.0f;
    for (int i = tid; i < 768; i += 256) bb[i] = b_hh[i];

    // stage weight tile 0
    #pragma unroll
    for (int j = 0; j < 12; ++j) {
        int f = (tid + j * 256) * 4;
        *(float4*)(W_s + f) = *(const float4*)(g_WhhT + f);
    }
    __syncthreads();

    ull acc[3][8][2];
    #pragma unroll
    for (int g = 0; g < 3; ++g)
        #pragma unroll
        for (int i = 0; i < 8; ++i) { acc[g][i][0] = 0ull; acc[g][i][1] = 0ull; }

    int buf = 0, nxt = 1;
    for (int t = 0; t < V_DIM; ++t) {
        for (int kt = 0; kt < 16; ++kt) {
            // stage next tile (weights identical every step -> mod-16 ring)
            {
                const float* src = g_WhhT + nxt * (16 * 768);
                float* dst = W_s + (buf ^ 1) * 12288;
                #pragma unroll
                for (int j = 0; j < 12; ++j) {
                    int f = (tid + j * 256) * 4;
                    *(float4*)(dst + f) = *(const float4*)(src + f);
                }
            }
            // compute this tile
            const float* Wb = W_s + buf * 12288;
            #pragma unroll
            for (int kk = 0; kk < 16; ++kk) {
                const int k = kt * 16 + kk;
                float4 a0 = *(const float4*)(A_s + k * ASTRIDE + r0);
                float4 a1 = *(const float4*)(A_s + k * ASTRIDE + r0 + 4);
                ull pa[8];
                pa[0] = pk2(a0.x); pa[1] = pk2(a0.y); pa[2] = pk2(a0.z); pa[3] = pk2(a0.w);
                pa[4] = pk2(a1.x); pa[5] = pk2(a1.y); pa[6] = pk2(a1.z); pa[7] = pk2(a1.w);
                #pragma unroll
                for (int g = 0; g < 3; ++g) {
                    ulonglong2 wv = *(const ulonglong2*)(Wb + kk * 768 + g * 256 + hcol);
                    #pragma unroll
                    for (int i = 0; i < 8; ++i) {
                        ffma2(acc[g][i][0], pa[i], wv.x);
                        ffma2(acc[g][i][1], pa[i], wv.y);
                    }
                }
            }
            __syncthreads();
            buf ^= 1;
            nxt = (nxt + 1) & 15;
        }

        // ---- epilogue: gates + state update (thread-exclusive cells) ----
        float4 bR = *(const float4*)(bb + 0 * 256 + hcol);
        float4 bZ = *(const float4*)(bb + 1 * 256 + hcol);
        float4 bN = *(const float4*)(bb + 2 * 256 + hcol);
        #pragma unroll
        for (int i = 0; i < 8; ++i) {
            size_t xrow = ((size_t)(b0 + r0 + i) * V_DIM + t) * 768;
            float4 xr = *(const float4*)(g_xg + xrow + 0 * 256 + hcol);
            float4 xz = *(const float4*)(g_xg + xrow + 1 * 256 + hcol);
            float4 xn = *(const float4*)(g_xg + xrow + 2 * 256 + hcol);
            float2 ar0 = upk(acc[0][i][0]), ar1 = upk(acc[0][i][1]);
            float2 az0 = upk(acc[1][i][0]), az1 = upk(acc[1][i][1]);
            float2 an0 = upk(acc[2][i][0]), an1 = upk(acc[2][i][1]);
            float rr[4], zz[4], nn[4];
            rr[0] = sigm(xr.x + ar0.x + bR.x);
            rr[1] = sigm(xr.y + ar0.y + bR.y);
            rr[2] = sigm(xr.z + ar1.x + bR.z);
            rr[3] = sigm(xr.w + ar1.y + bR.w);
            zz[0] = sigm(xz.x + az0.x + bZ.x);
            zz[1] = sigm(xz.y + az0.y + bZ.y);
            zz[2] = sigm(xz.z + az1.x + bZ.z);
            zz[3] = sigm(xz.w + az1.y + bZ.w);
            nn[0] = tanhfast(xn.x + rr[0] * (an0.x + bN.x));
            nn[1] = tanhfast(xn.y + rr[1] * (an0.y + bN.y));
            nn[2] = tanhfast(xn.z + rr[2] * (an1.x + bN.z));
            nn[3] = tanhfast(xn.w + rr[3] * (an1.y + bN.w));
            #pragma unroll
            for (int c = 0; c < 4; ++c) {
                float* hp = A_s + (hcol + c) * ASTRIDE + r0 + i;
                float h = *hp;
                *hp = nn[c] + zz[c] * (h - nn[c]);
            }
        }
        #pragma unroll
        for (int g = 0; g < 3; ++g)
            #pragma unroll
            for (int i = 0; i < 8; ++i) { acc[g][i][0] = 0ull; acc[g][i][1] = 0ull; }
        __syncthreads();
    }

    // ---- write xcat = [h(256) | feat(15) | pad(1)] ----
    #pragma unroll
    for (int i = 0; i < 8; ++i) {
        float4 v;
        v.x = A_s[(hcol + 0) * ASTRIDE + r0 + i];
        v.y = A_s[(hcol + 1) * ASTRIDE + r0 + i];
        v.z = A_s[(hcol + 2) * ASTRIDE + r0 + i];
        v.w = A_s[(hcol + 3) * ASTRIDE + r0 + i];
        *(float4*)&g_xcat[(size_t)(b0 + r0 + i) * 272 + hcol] = v;
    }
    // FIX (R8 bug): 480 feature slots, only 256 threads -> grid-stride loop
    for (int idx = tid; idx < 32 * F_DIM; idx += 256) {
        int row = idx / F_DIM, f = idx - row * F_DIM;
        g_xcat[(size_t)(b0 + row) * 272 + 256 + f] =
            state[((size_t)(b0 + row) * V_DIM) * F_DIM + f];
    }
    if (tid < 32) g_xcat[(size_t)(b0 + tid) * 272 + 271] = 0.0f;
}

// ---------------------------------------------------------------------------
// GEMM: C[M][N] = act(A[M][K] @ Wt[K][N] + bias). 128x128 tile, BK=16,
// 256 threads, thread = 8 rows x cols {4tx..4tx+3, 64+4tx..+3} (conflict-free).
// ---------------------------------------------------------------------------
__global__ __launch_bounds__(256, 2)
void mlp_gemm(const float* __restrict__ A, const float* __restrict__ Wt,
              const float* __restrict__ bias, float* __restrict__ C,
              int K, int N, int relu)
{
    __shared__ __align__(16) float A_s[2][16 * 128];
    __shared__ __align__(16) float W_s[2][16 * 128];

    const int tid  = threadIdx.x;
    const int tx   = tid & 15, ty = tid >> 4;
    const int m0   = blockIdx.y << 7, n0 = blockIdx.x << 7;
    const int crow = ty * 8;
    const int c1   = 4 * tx, c2 = 64 + 4 * tx;

    ull acc[8][4];
    #pragma unroll
    for (int j = 0; j < 8; ++j)
        #pragma unroll
        for (int c = 0; c < 4; ++c) acc[j][c] = 0ull;

    const int ar = tid >> 1;
    const int ac = (tid & 1) * 8;
    const int wk = ty;
    const int wc = 8 * tx;

    {   // prologue stage tile 0
        const float* sa = A + (size_t)(m0 + ar) * K + ac;
        float4 a0 = *(const float4*)sa, a1 = *(const float4*)(sa + 4);
        A_s[0][(ac+0)*128+ar]=a0.x; A_s[0][(ac+1)*128+ar]=a0.y;
        A_s[0][(ac+2)*128+ar]=a0.z; A_s[0][(ac+3)*128+ar]=a0.w;
        A_s[0][(ac+4)*128+ar]=a1.x; A_s[0][(ac+5)*128+ar]=a1.y;
        A_s[0][(ac+6)*128+ar]=a1.z; A_s[0][(ac+7)*128+ar]=a1.w;
        const float* sw = Wt + (size_t)wk * N + n0 + wc;
        *(float4*)&W_s[0][wk*128+wc]   = *(const float4*)sw;
        *(float4*)&W_s[0][wk*128+wc+4] = *(const float4*)(sw + 4);
    }
    __syncthreads();

    const int ntile = K >> 4;
    for (int tk = 0; tk < ntile; ++tk) {
        const int cb = tk & 1;
        if (tk + 1 < ntile) {
            const int nb = cb ^ 1, k0 = (tk + 1) << 4;
            const float* sa = A + (size_t)(m0 + ar) * K + k0 + ac;
            float4 a0 = *(const float4*)sa, a1 = *(const float4*)(sa + 4);
            A_s[nb][(ac+0)*128+ar]=a0.x; A_s[nb][(ac+1)*128+ar]=a0.y;
            A_s[nb][(ac+2)*128+ar]=a0.z; A_s[nb][(ac+3)*128+ar]=a0.w;
            A_s[nb][(ac+4)*128+ar]=a1.x; A_s[nb][(ac+5)*128+ar]=a1.y;
            A_s[nb][(ac+6)*128+ar]=a1.z; A_s[nb][(ac+7)*128+ar]=a1.w;
            const float* sw = Wt + (size_t)(k0 + wk) * N + n0 + wc;
            *(float4*)&W_s[nb][wk*128+wc]   = *(const float4*)sw;
            *(float4*)&W_s[nb][wk*128+wc+4] = *(const float4*)(sw + 4);
        }
        #pragma unroll
        for (int k = 0; k < 16; ++k) {
            float4 a0 = *(const float4*)&A_s[cb][k * 128 + crow];
            float4 a1 = *(const float4*)&A_s[cb][k * 128 + crow + 4];
            ulonglong2 w1 = *(const ulonglong2*)&W_s[cb][k * 128 + c1];
            ulonglong2 w2 = *(const ulonglong2*)&W_s[cb][k * 128 + c2];
            float av[8] = {a0.x, a0.y, a0.z, a0.w, a1.x, a1.y, a1.z, a1.w};
            #pragma unroll
            for (int j = 0; j < 8; ++j) {
                ull pa = pk2(av[j]);
                ffma2(acc[j][0], pa, w1.x);
                ffma2(acc[j][1], pa, w1.y);
                ffma2(acc[j][2], pa, w2.x);
                ffma2(acc[j][3], pa, w2.y);
            }
        }
        __syncthreads();
    }

    float4 bv1 = *(const float4*)(bias + n0 + c1);
    float4 bv2 = *(const float4*)(bias + n0 + c2);
    float bvf1[4] = {bv1.x, bv1.y, bv1.z, bv1.w};
    float bvf2[4] = {bv2.x, bv2.y, bv2.z, bv2.w};
    #pragma unroll
    for (int j = 0; j < 8; ++j) {
        float o1[4], o2[4];
        {
            float2 v0 = upk(acc[j][0]), v1 = upk(acc[j][1]);
            o1[0] = v0.x + bvf1[0]; o1[1] = v0.y + bvf1[1];
            o1[2] = v1.x + bvf1[2]; o1[3] = v1.y + bvf1[3];
            float2 u0 = upk(acc[j][2]), u1 = upk(acc[j][3]);
            o2[0] = u0.x + bvf2[0]; o2[1] = u0.y + bvf2[1];
            o2[2] = u1.x + bvf2[2]; o2[3] = u1.y + bvf2[3];
        }
        if (relu) {
            #pragma unroll
            for (int c = 0; c < 4; ++c) {
                o1[c] = fmaxf(o1[c], 0.0f);
                o2[c] = fmaxf(o2[c], 0.0f);
            }
        }
        float* dst = C + (size_t)(m0 + crow + j) * N + n0;
        *(float4*)(dst + c1) = make_float4(o1[0], o1[1], o1[2], o1[3]);
        *(float4*)(dst + c2) = make_float4(o2[0], o2[1], o2[2], o2[3]);
    }
}

// ---------------------------------------------------------------------------
// Head: out[b] = tanh(dot(a4[b], Wp) + bp)
// ---------------------------------------------------------------------------
__global__ void head_kernel(const float* __restrict__ A, const float* __restrict__ Wp,
                            const float* __restrict__ bp, float* __restrict__ out)
{
    __shared__ float wsh[256];
    int tid = threadIdx.x;
    wsh[tid] = Wp[tid];
    __syncthreads();
    int warp = tid >> 5, lane = tid & 31;
    int b = blockIdx.x * 8 + warp;
    const float* a = A + (size_t)b * 256;
    float s = 0.0f;
    #pragma unroll
    for (int i = 0; i < 8; ++i) s += a[lane + 32 * i] * wsh[lane + 32 * i];
    #pragma unroll
    for (int o = 16; o; o >>= 1) s += __shfl_xor_sync(0xffffffffu, s, o);
    if (lane == 0) out[b] = tanhf(s + bp[0]);
}

// ---------------------------------------------------------------------------
// Launch
// ---------------------------------------------------------------------------
extern "C" void kernel_launch(void* const* d_in, const int* in_sizes, int n_in,
                              void* d_out, int out_size)
{
    const float* state = (const float*)d_in[0];
    const float* W_ih  = (const float*)d_in[1];
    const float* W_hh  = (const float*)d_in[2];
    const float* b_ih  = (const float*)d_in[3];
    const float* b_hh  = (const float*)d_in[4];
    const float* W1 = (const float*)d_in[5];  const float* b1 = (const float*)d_in[6];
    const float* W2 = (const float*)d_in[7];  const float* b2 = (const float*)d_in[8];
    const float* W3 = (const float*)d_in[9];  const float* b3 = (const float*)d_in[10];
    const float* W4 = (const float*)d_in[11]; const float* b4 = (const float*)d_in[12];
    const float* Wp = (const float*)d_in[13]; const float* bp = (const float*)d_in[14];
    float* out = (float*)d_out;

    float *pWhhT, *pWihT, *pW1t, *pW2t, *pW3t, *pW4t;
    float *pS16, *pXg, *pXcat, *pA, *pB;
    cudaGetSymbolAddress((void**)&pWhhT, g_WhhT);
    cudaGetSymbolAddress((void**)&pWihT, g_WihT);
    cudaGetSymbolAddress((void**)&pW1t,  g_W1t);
    cudaGetSymbolAddress((void**)&pW2t,  g_W2t);
    cudaGetSymbolAddress((void**)&pW3t,  g_W3t);
    cudaGetSymbolAddress((void**)&pW4t,  g_W4t);
    cudaGetSymbolAddress((void**)&pS16,  g_state16);
    cudaGetSymbolAddress((void**)&pXg,   g_xg);
    cudaGetSymbolAddress((void**)&pXcat, g_xcat);
    cudaGetSymbolAddress((void**)&pA,    g_actA);
    cudaGetSymbolAddress((void**)&pB,    g_actB);

    cudaFuncSetAttribute(gru_kernel, cudaFuncAttributeMaxDynamicSharedMemorySize,
                         GRU_SMEM_BYTES);

    // prep
    transpose_pad<<<(256 * 768 + 255) / 256, 256>>>(W_hh, pWhhT, 768, 256, 256);
    transpose_pad<<<(16 * 768 + 255) / 256, 256>>>(W_ih, pWihT, 768, 15, 16);
    pad_state16<<<(B_SZ * V_DIM * 16 + 255) / 256, 256>>>(state, pS16);
    transpose_w1<<<(272 * 1024 + 255) / 256, 256>>>(W1, pW1t);
    transpose_pad<<<(1024 * 1024 + 255) / 256, 256>>>(W2, pW2t, 1024, 1024, 1024);
    transpose_pad<<<(1024 * 512 + 255) / 256, 256>>>(W3, pW3t, 512, 1024, 1024);
    transpose_pad<<<(512 * 256 + 255) / 256, 256>>>(W4, pW4t, 256, 512, 512);

    // xg = state @ W_ih^T + b_ih  (M = B*V = 327680, K = 16, N = 768)
    mlp_gemm<<<dim3(6, 2560), 256>>>(pS16, pWihT, b_ih, pXg, 16, 768, 0);

    // GRU over V=20, writes g_xcat [B][272]
    gru_kernel<<<B_SZ / 32, 256, GRU_SMEM_BYTES>>>(state, b_hh);

    // MLP (relu on)
    mlp_gemm<<<dim3(8, 128), 256>>>(pXcat, pW1t, b1, pA, 272, 1024, 1);
    mlp_gemm<<<dim3(8, 128), 256>>>(pA,    pW2t, b2, pB, 1024, 1024, 1);
    mlp_gemm<<<dim3(4, 128), 256>>>(pB,    pW3t, b3, pA, 1024, 512, 1);
    mlp_gemm<<<dim3(2, 128), 256>>>(pA,    pW4t, b4, pB, 512, 256, 1);

    // head
    head_kernel<<<B_SZ / 8, 256>>>(pB, Wp, bp, out);
}

// round 12
// speedup vs baseline: 2.9328x; 1.1114x over previous
#include <cuda_runtime.h>
#include <cuda_bf16.h>
#include <cstdint>

typedef unsigned long long ull;

#define B_SZ  16384
#define V_DIM 20
#define F_DIM 15

// ---------------------------------------------------------------------------
// f32x2 packed math helpers (fp32 GRU path)
// ---------------------------------------------------------------------------
__device__ __forceinline__ ull pk2(float a) {
    ull r; asm("mov.b64 %0, {%1, %1};" : "=l"(r) : "f"(a)); return r;
}
__device__ __forceinline__ void ffma2(ull &d, ull a, ull b) {
    asm("fma.rn.f32x2 %0, %1, %2, %0;" : "+l"(d) : "l"(a), "l"(b));
}
__device__ __forceinline__ float2 upk(ull v) {
    float2 f; asm("mov.b64 {%0, %1}, %2;" : "=f"(f.x), "=f"(f.y) : "l"(v)); return f;
}
__device__ __forceinline__ float sigm(float x) {
    return __fdividef(1.0f, 1.0f + __expf(-x));
}
__device__ __forceinline__ float tanhfast(float x) {
    float y; asm("tanh.approx.f32 %0, %1;" : "=f"(y) : "f"(x)); return y;
}

// ---------------------------------------------------------------------------
// mma.sync helpers (sm_80+ PTX: legal on compute_103, unlike tcgen05)
// ---------------------------------------------------------------------------
__device__ __forceinline__ uint32_t smem_u32(const void* p) {
    uint32_t a;
    asm("{ .reg .u64 t; cvta.to.shared.u64 t, %1; cvt.u32.u64 %0, t; }"
        : "=r"(a) : "l"(p));
    return a;
}
__device__ __forceinline__ void ldm4(uint32_t* r, uint32_t addr) {
    asm volatile("ldmatrix.sync.aligned.m8n8.x4.shared.b16 {%0,%1,%2,%3}, [%4];"
                 : "=r"(r[0]), "=r"(r[1]), "=r"(r[2]), "=r"(r[3]) : "r"(addr));
}
__device__ __forceinline__ void mma16816(float* c, const uint32_t* a,
                                         uint32_t b0, uint32_t b1) {
    asm volatile(
        "mma.sync.aligned.m16n8k16.row.col.f32.bf16.bf16.f32 "
        "{%0,%1,%2,%3}, {%4,%5,%6,%7}, {%8,%9}, {%0,%1,%2,%3};"
        : "+f"(c[0]), "+f"(c[1]), "+f"(c[2]), "+f"(c[3])
        : "r"(a[0]), "r"(a[1]), "r"(a[2]), "r"(a[3]), "r"(b0), "r"(b1));
}

// ---------------------------------------------------------------------------
// Device-global scratch
// ---------------------------------------------------------------------------
__device__ float g_WhhT[256 * 768];
__device__ float g_WihT[16 * 768];
__device__ float g_state16[(size_t)B_SZ * V_DIM * 16];
__device__ float g_xg[(size_t)B_SZ * V_DIM * 768];
__device__ float g_xcat[(size_t)B_SZ * 272];
__device__ float g_out4[(size_t)B_SZ * 256];

// bf16 split buffers (16B-aligned for uint4 access)
__device__ __align__(16) __nv_bfloat16 g_xh[(size_t)B_SZ * 320];
__device__ __align__(16) __nv_bfloat16 g_xl[(size_t)B_SZ * 320];
__device__ __align__(16) __nv_bfloat16 g_ah[(size_t)B_SZ * 1024];
__device__ __align__(16) __nv_bfloat16 g_al[(size_t)B_SZ * 1024];
__device__ __align__(16) __nv_bfloat16 g_bh[(size_t)B_SZ * 1024];
__device__ __align__(16) __nv_bfloat16 g_bl[(size_t)B_SZ * 1024];
__device__ __align__(16) __nv_bfloat16 g_w1h[1024 * 320];
__device__ __align__(16) __nv_bfloat16 g_w1l[1024 * 320];
__device__ __align__(16) __nv_bfloat16 g_w2h[1024 * 1024];
__device__ __align__(16) __nv_bfloat16 g_w2l[1024 * 1024];
__device__ __align__(16) __nv_bfloat16 g_w3h[512 * 1024];
__device__ __align__(16) __nv_bfloat16 g_w3l[512 * 1024];
__device__ __align__(16) __nv_bfloat16 g_w4h[256 * 512];
__device__ __align__(16) __nv_bfloat16 g_w4l[256 * 512];

// ---------------------------------------------------------------------------
// Prep kernels
// ---------------------------------------------------------------------------
__global__ void transpose_pad(const float* __restrict__ in, float* __restrict__ out,
                              int N, int K, int Kp)
{
    int idx = blockIdx.x * 256 + threadIdx.x;
    if (idx >= Kp * N) return;
    int k = idx / N, n = idx - k * N;
    out[idx] = (k < K) ? in[n * K + k] : 0.0f;
}

__global__ void pad_state16(const float* __restrict__ s, float* __restrict__ o)
{
    int idx = blockIdx.x * 256 + threadIdx.x;
    if (idx >= B_SZ * V_DIM * 16) return;
    int r = idx >> 4, c = idx & 15;
    o[idx] = (c < F_DIM) ? s[r * F_DIM + c] : 0.0f;
}

// generic bf16 hi/lo split with K padding: in [N][K] -> out [N][Kp]
__global__ void split_pad(const float* __restrict__ in,
                          __nv_bfloat16* __restrict__ hi, __nv_bfloat16* __restrict__ lo,
                          int N, int K, int Kp)
{
    int idx = blockIdx.x * 256 + threadIdx.x;
    if (idx >= N * Kp) return;
    int n = idx / Kp, k = idx - n * Kp;
    float v = (k < K) ? in[(size_t)n * K + k] : 0.0f;
    __nv_bfloat16 h = __float2bfloat16(v);
    hi[idx] = h;
    lo[idx] = __float2bfloat16(v - __bfloat162float(h));
}

// W1 split with column permutation matching xcat = [h(256)|feat(15)|pad]
__global__ void split_w1(const float* __restrict__ W1,
                         __nv_bfloat16* __restrict__ hi, __nv_bfloat16* __restrict__ lo)
{
    int idx = blockIdx.x * 256 + threadIdx.x;
    if (idx >= 1024 * 320) return;
    int n = idx / 320, k = idx - n * 320;
    float v = 0.0f;
    if (k < 256)      v = W1[n * 271 + 15 + k];
    else if (k < 271) v = W1[n * 271 + (k - 256)];
    __nv_bfloat16 h = __float2bfloat16(v);
    hi[idx] = h;
    lo[idx] = __float2bfloat16(v - __bfloat162float(h));
}

// ---------------------------------------------------------------------------
// GRU kernel (unchanged from R9 passing version)
// ---------------------------------------------------------------------------
#define ASTRIDE 36
#define GRU_SMEM_FLOATS (2 * 16 * 768 + 256 * ASTRIDE + 768)
#define GRU_SMEM_BYTES  (GRU_SMEM_FLOATS * 4)

__global__ __launch_bounds__(256, 1)
void gru_kernel(const float* __restrict__ state, const float* __restrict__ b_hh)
{
    extern __shared__ __align__(16) float sm[];
    float* W_s = sm;
    float* A_s = sm + 2 * 16 * 768;
    float* bb  = A_s + 256 * ASTRIDE;

    const int tid  = threadIdx.x;
    const int w    = tid >> 5, lane = tid & 31;
    const int cg   = w & 1, rg = w >> 1;
    const int r0   = rg * 8;
    const int hcol = cg * 128 + lane * 4;
    const int b0   = blockIdx.x * 32;

    for (int i = tid; i < 256 * ASTRIDE; i += 256) A_s[i] = 0.0f;
    for (int i = tid; i < 768; i += 256) bb[i] = b_hh[i];

    #pragma unroll
    for (int j = 0; j < 12; ++j) {
        int f = (tid + j * 256) * 4;
        *(float4*)(W_s + f) = *(const float4*)(g_WhhT + f);
    }
    __syncthreads();

    ull acc[3][8][2];
    #pragma unroll
    for (int g = 0; g < 3; ++g)
        #pragma unroll
        for (int i = 0; i < 8; ++i) { acc[g][i][0] = 0ull; acc[g][i][1] = 0ull; }

    int buf = 0, nxt = 1;
    for (int t = 0; t < V_DIM; ++t) {
        for (int kt = 0; kt < 16; ++kt) {
            {
                const float* src = g_WhhT + nxt * (16 * 768);
                float* dst = W_s + (buf ^ 1) * 12288;
                #pragma unroll
                for (int j = 0; j < 12; ++j) {
                    int f = (tid + j * 256) * 4;
                    *(float4*)(dst + f) = *(const float4*)(src + f);
                }
            }
            const float* Wb = W_s + buf * 12288;
            #pragma unroll
            for (int kk = 0; kk < 16; ++kk) {
                const int k = kt * 16 + kk;
                float4 a0 = *(const float4*)(A_s + k * ASTRIDE + r0);
                float4 a1 = *(const float4*)(A_s + k * ASTRIDE + r0 + 4);
                ull pa[8];
                pa[0] = pk2(a0.x); pa[1] = pk2(a0.y); pa[2] = pk2(a0.z); pa[3] = pk2(a0.w);
                pa[4] = pk2(a1.x); pa[5] = pk2(a1.y); pa[6] = pk2(a1.z); pa[7] = pk2(a1.w);
                #pragma unroll
                for (int g = 0; g < 3; ++g) {
                    ulonglong2 wv = *(const ulonglong2*)(Wb + kk * 768 + g * 256 + hcol);
                    #pragma unroll
                    for (int i = 0; i < 8; ++i) {
                        ffma2(acc[g][i][0], pa[i], wv.x);
                        ffma2(acc[g][i][1], pa[i], wv.y);
                    }
                }
            }
            __syncthreads();
            buf ^= 1;
            nxt = (nxt + 1) & 15;
        }

        float4 bR = *(const float4*)(bb + 0 * 256 + hcol);
        float4 bZ = *(const float4*)(bb + 1 * 256 + hcol);
        float4 bN = *(const float4*)(bb + 2 * 256 + hcol);
        #pragma unroll
        for (int i = 0; i < 8; ++i) {
            size_t xrow = ((size_t)(b0 + r0 + i) * V_DIM + t) * 768;
            float4 xr = *(const float4*)(g_xg + xrow + 0 * 256 + hcol);
            float4 xz = *(const float4*)(g_xg + xrow + 1 * 256 + hcol);
            float4 xn = *(const float4*)(g_xg + xrow + 2 * 256 + hcol);
            float2 ar0 = upk(acc[0][i][0]), ar1 = upk(acc[0][i][1]);
            float2 az0 = upk(acc[1][i][0]), az1 = upk(acc[1][i][1]);
            float2 an0 = upk(acc[2][i][0]), an1 = upk(acc[2][i][1]);
            float rr[4], zz[4], nn[4];
            rr[0] = sigm(xr.x + ar0.x + bR.x);
            rr[1] = sigm(xr.y + ar0.y + bR.y);
            rr[2] = sigm(xr.z + ar1.x + bR.z);
            rr[3] = sigm(xr.w + ar1.y + bR.w);
            zz[0] = sigm(xz.x + az0.x + bZ.x);
            zz[1] = sigm(xz.y + az0.y + bZ.y);
            zz[2] = sigm(xz.z + az1.x + bZ.z);
            zz[3] = sigm(xz.w + az1.y + bZ.w);
            nn[0] = tanhfast(xn.x + rr[0] * (an0.x + bN.x));
            nn[1] = tanhfast(xn.y + rr[1] * (an0.y + bN.y));
            nn[2] = tanhfast(xn.z + rr[2] * (an1.x + bN.z));
            nn[3] = tanhfast(xn.w + rr[3] * (an1.y + bN.w));
            #pragma unroll
            for (int c = 0; c < 4; ++c) {
                float* hp = A_s + (hcol + c) * ASTRIDE + r0 + i;
                float h = *hp;
                *hp = nn[c] + zz[c] * (h - nn[c]);
            }
        }
        #pragma unroll
        for (int g = 0; g < 3; ++g)
            #pragma unroll
            for (int i = 0; i < 8; ++i) { acc[g][i][0] = 0ull; acc[g][i][1] = 0ull; }
        __syncthreads();
    }

    #pragma unroll
    for (int i = 0; i < 8; ++i) {
        float4 v;
        v.x = A_s[(hcol + 0) * ASTRIDE + r0 + i];
        v.y = A_s[(hcol + 1) * ASTRIDE + r0 + i];
        v.z = A_s[(hcol + 2) * ASTRIDE + r0 + i];
        v.w = A_s[(hcol + 3) * ASTRIDE + r0 + i];
        *(float4*)&g_xcat[(size_t)(b0 + r0 + i) * 272 + hcol] = v;
    }
    for (int idx = tid; idx < 32 * F_DIM; idx += 256) {
        int row = idx / F_DIM, f = idx - row * F_DIM;
        g_xcat[(size_t)(b0 + row) * 272 + 256 + f] =
            state[((size_t)(b0 + row) * V_DIM) * F_DIM + f];
    }
    if (tid < 32) g_xcat[(size_t)(b0 + tid) * 272 + 271] = 0.0f;
}

// ---------------------------------------------------------------------------
// fp32 GEMM (kept for the xg precompute: K=16, N=768)
// ---------------------------------------------------------------------------
__global__ __launch_bounds__(256, 2)
void mlp_gemm(const float* __restrict__ A, const float* __restrict__ Wt,
              const float* __restrict__ bias, float* __restrict__ C,
              int K, int N, int relu)
{
    __shared__ __align__(16) float A_s[2][16 * 128];
    __shared__ __align__(16) float W_s[2][16 * 128];

    const int tid  = threadIdx.x;
    const int tx   = tid & 15, ty = tid >> 4;
    const int m0   = blockIdx.y << 7, n0 = blockIdx.x << 7;
    const int crow = ty * 8;
    const int c1   = 4 * tx, c2 = 64 + 4 * tx;

    ull acc[8][4];
    #pragma unroll
    for (int j = 0; j < 8; ++j)
        #pragma unroll
        for (int c = 0; c < 4; ++c) acc[j][c] = 0ull;

    const int ar = tid >> 1;
    const int ac = (tid & 1) * 8;
    const int wk = ty;
    const int wc = 8 * tx;

    {
        const float* sa = A + (size_t)(m0 + ar) * K + ac;
        float4 a0 = *(const float4*)sa, a1 = *(const float4*)(sa + 4);
        A_s[0][(ac+0)*128+ar]=a0.x; A_s[0][(ac+1)*128+ar]=a0.y;
        A_s[0][(ac+2)*128+ar]=a0.z; A_s[0][(ac+3)*128+ar]=a0.w;
        A_s[0][(ac+4)*128+ar]=a1.x; A_s[0][(ac+5)*128+ar]=a1.y;
        A_s[0][(ac+6)*128+ar]=a1.z; A_s[0][(ac+7)*128+ar]=a1.w;
        const float* sw = Wt + (size_t)wk * N + n0 + wc;
        *(float4*)&W_s[0][wk*128+wc]   = *(const float4*)sw;
        *(float4*)&W_s[0][wk*128+wc+4] = *(const float4*)(sw + 4);
    }
    __syncthreads();

    const int ntile = K >> 4;
    for (int tk = 0; tk < ntile; ++tk) {
        const int cb = tk & 1;
        if (tk + 1 < ntile) {
            const int nb = cb ^ 1, k0 = (tk + 1) << 4;
            const float* sa = A + (size_t)(m0 + ar) * K + k0 + ac;
            float4 a0 = *(const float4*)sa, a1 = *(const float4*)(sa + 4);
            A_s[nb][(ac+0)*128+ar]=a0.x; A_s[nb][(ac+1)*128+ar]=a0.y;
            A_s[nb][(ac+2)*128+ar]=a0.z; A_s[nb][(ac+3)*128+ar]=a0.w;
            A_s[nb][(ac+4)*128+ar]=a1.x; A_s[nb][(ac+5)*128+ar]=a1.y;
            A_s[nb][(ac+6)*128+ar]=a1.z; A_s[nb][(ac+7)*128+ar]=a1.w;
            const float* sw = Wt + (size_t)(k0 + wk) * N + n0 + wc;
            *(float4*)&W_s[nb][wk*128+wc]   = *(const float4*)sw;
            *(float4*)&W_s[nb][wk*128+wc+4] = *(const float4*)(sw + 4);
        }
        #pragma unroll
        for (int k = 0; k < 16; ++k) {
            float4 a0 = *(const float4*)&A_s[cb][k * 128 + crow];
            float4 a1 = *(const float4*)&A_s[cb][k * 128 + crow + 4];
            ulonglong2 w1 = *(const ulonglong2*)&W_s[cb][k * 128 + c1];
            ulonglong2 w2 = *(const ulonglong2*)&W_s[cb][k * 128 + c2];
            float av[8] = {a0.x, a0.y, a0.z, a0.w, a1.x, a1.y, a1.z, a1.w};
            #pragma unroll
            for (int j = 0; j < 8; ++j) {
                ull pa = pk2(av[j]);
                ffma2(acc[j][0], pa, w1.x);
                ffma2(acc[j][1], pa, w1.y);
                ffma2(acc[j][2], pa, w2.x);
                ffma2(acc[j][3], pa, w2.y);
            }
        }
        __syncthreads();
    }

    float4 bv1 = *(const float4*)(bias + n0 + c1);
    float4 bv2 = *(const float4*)(bias + n0 + c2);
    float bvf1[4] = {bv1.x, bv1.y, bv1.z, bv1.w};
    float bvf2[4] = {bv2.x, bv2.y, bv2.z, bv2.w};
    #pragma unroll
    for (int j = 0; j < 8; ++j) {
        float o1[4], o2[4];
        {
            float2 v0 = upk(acc[j][0]), v1 = upk(acc[j][1]);
            o1[0] = v0.x + bvf1[0]; o1[1] = v0.y + bvf1[1];
            o1[2] = v1.x + bvf1[2]; o1[3] = v1.y + bvf1[3];
            float2 u0 = upk(acc[j][2]), u1 = upk(acc[j][3]);
            o2[0] = u0.x + bvf2[0]; o2[1] = u0.y + bvf2[1];
            o2[2] = u1.x + bvf2[2]; o2[3] = u1.y + bvf2[3];
        }
        if (relu) {
            #pragma unroll
            for (int c = 0; c < 4; ++c) {
                o1[c] = fmaxf(o1[c], 0.0f);
                o2[c] = fmaxf(o2[c], 0.0f);
            }
        }
        float* dst = C + (size_t)(m0 + crow + j) * N + n0;
        *(float4*)(dst + c1) = make_float4(o1[0], o1[1], o1[2], o1[3]);
        *(float4*)(dst + c2) = make_float4(o2[0], o2[1], o2[2], o2[3]);
    }
}

// ---------------------------------------------------------------------------
// Warp-MMA bf16-split GEMM: C = relu(A @ B^T + bias)
// A: [M][Kp] hi/lo bf16 row-major; B = W: [N][Kp] hi/lo bf16 row-major.
// CTA 128x128, 256 threads = 8 warps (4m x 2n), warp tile 32x64.
// K staged in 64-wide tiles; smem rows stride 72 bf16 (144B) -> every
// ldmatrix (8 rows x 16B) is bank-conflict-free without swizzle.
// 3 HMMA per (m,n,k) block: Ah*Bh + Ah*Bl + Al*Bh (al*bl dropped ~2^-17).
// ---------------------------------------------------------------------------
#define WMG_TILE_E  (128 * 72)               // bf16 per operand tile
#define WMG_TILE_B  (WMG_TILE_E * 2)         // bytes = 18432
#define WMG_BUF_B   (4 * WMG_TILE_B)         // bytes = 73728
#define WMG_SMEM    (2 * WMG_BUF_B)          // 147456 bytes

__global__ __launch_bounds__(256, 1)
void wm_gemm(const __nv_bfloat16* __restrict__ Ah, const __nv_bfloat16* __restrict__ Al,
             const __nv_bfloat16* __restrict__ Bh, const __nv_bfloat16* __restrict__ Bl,
             const float* __restrict__ bias,
             __nv_bfloat16* __restrict__ Ch, __nv_bfloat16* __restrict__ Cl,
             float* __restrict__ Cf, int Kp, int N)
{
    extern __shared__ __align__(16) __nv_bfloat16 sw[];
    const int tid  = threadIdx.x;
    const int w    = tid >> 5, lane = tid & 31;
    const int wm   = w & 3, wn = w >> 2;
    const int m0   = blockIdx.y << 7, n0 = blockIdx.x << 7;
    const int m0c  = wm * 32, n0c = wn * 64;

    float acc[2][8][4];
    #pragma unroll
    for (int mb = 0; mb < 2; ++mb)
        #pragma unroll
        for (int j = 0; j < 8; ++j)
            #pragma unroll
            for (int c = 0; c < 4; ++c) acc[mb][j][c] = 0.0f;

    const uint32_t sbase = smem_u32(sw);
    // per-lane ldmatrix byte offsets within an operand tile
    const uint32_t aByte =
        ((uint32_t)(m0c + ((lane >> 3) & 1) * 8 + (lane & 7)) * 72 + (lane >> 4) * 8) * 2;
    const uint32_t bByte =
        ((uint32_t)(n0c + (lane >> 4) * 8 + (lane & 7)) * 72 + ((lane >> 3) & 1) * 8) * 2;

    // staging: thread covers 4 16B-chunks of each operand tile
    const int srow = tid >> 1;
    const int sc8  = (tid & 1) * 4;

    auto stage = [&](int t, int buf) {
        const int koff = t * 64 + sc8 * 8;
        __nv_bfloat16* dst = sw + (size_t)buf * (WMG_BUF_B / 2) + srow * 72 + sc8 * 8;
        const __nv_bfloat16* s0 = Ah + (size_t)(m0 + srow) * Kp + koff;
        const __nv_bfloat16* s1 = Al + (size_t)(m0 + srow) * Kp + koff;
        const __nv_bfloat16* s2 = Bh + (size_t)(n0 + srow) * Kp + koff;
        const __nv_bfloat16* s3 = Bl + (size_t)(n0 + srow) * Kp + koff;
        #pragma unroll
        for (int q = 0; q < 4; ++q) {
            *(uint4*)(dst + q * 8)                    = *(const uint4*)(s0 + q * 8);
            *(uint4*)(dst + WMG_TILE_E + q * 8)       = *(const uint4*)(s1 + q * 8);
            *(uint4*)(dst + 2 * WMG_TILE_E + q * 8)   = *(const uint4*)(s2 + q * 8);
            *(uint4*)(dst + 3 * WMG_TILE_E + q * 8)   = *(const uint4*)(s3 + q * 8);
        }
    };

    stage(0, 0);
    __syncthreads();

    const int T = Kp >> 6;
    for (int t = 0; t < T; ++t) {
        const int buf = t & 1;
        if (t + 1 < T) stage(t + 1, buf ^ 1);

        const uint32_t ab = sbase + buf * WMG_BUF_B;
        #pragma unroll
        for (int kk = 0; kk < 4; ++kk) {
            uint32_t a0h[4], a1h[4], a0l[4], a1l[4];
            const uint32_t ak = ab + aByte + kk * 32;
            ldm4(a0h, ak);
            ldm4(a1h, ak + 2304);                 // +16 rows (16*144B)
            ldm4(a0l, ak + WMG_TILE_B);
            ldm4(a1l, ak + WMG_TILE_B + 2304);
            #pragma unroll
            for (int jj = 0; jj < 4; ++jj) {
                uint32_t bh[4], bl[4];
                const uint32_t bk = ab + 2 * WMG_TILE_B + bByte + jj * 2304 + kk * 32;
                ldm4(bh, bk);
                ldm4(bl, bk + WMG_TILE_B);
                // n-block j = 2*jj uses b[0..1]; j+1 uses b[2..3]
                mma16816(acc[0][2*jj],     a0h, bh[0], bh[1]);
                mma16816(acc[0][2*jj],     a0h, bl[0], bl[1]);
                mma16816(acc[0][2*jj],     a0l, bh[0], bh[1]);
                mma16816(acc[0][2*jj + 1], a0h, bh[2], bh[3]);
                mma16816(acc[0][2*jj + 1], a0h, bl[2], bl[3]);
                mma16816(acc[0][2*jj + 1], a0l, bh[2], bh[3]);
                mma16816(acc[1][2*jj],     a1h, bh[0], bh[1]);
                mma16816(acc[1][2*jj],     a1h, bl[0], bl[1]);
                mma16816(acc[1][2*jj],     a1l, bh[0], bh[1]);
                mma16816(acc[1][2*jj + 1], a1h, bh[2], bh[3]);
                mma16816(acc[1][2*jj + 1], a1h, bl[2], bl[3]);
                mma16816(acc[1][2*jj + 1], a1l, bh[2], bh[3]);
            }
        }
        __syncthreads();
    }

    // epilogue: thread owns rows {lr, lr+8} of each m16 block, col pair lc
    const int lr = lane >> 2;
    const int lc = (lane & 3) * 2;
    #pragma unroll
    for (int mb = 0; mb < 2; ++mb) {
        const int r0g = m0 + m0c + 16 * mb + lr;
        const int r1g = r0g + 8;
        #pragma unroll
        for (int j = 0; j < 8; ++j) {
            const int nc = n0 + n0c + 8 * j + lc;
            float2 bv = *(const float2*)(bias + nc);
            float v00 = fmaxf(acc[mb][j][0] + bv.x, 0.0f);
            float v01 = fmaxf(acc[mb][j][1] + bv.y, 0.0f);
            float v10 = fmaxf(acc[mb][j][2] + bv.x, 0.0f);
            float v11 = fmaxf(acc[mb][j][3] + bv.y, 0.0f);
            if (Cf) {
                *(float2*)(Cf + (size_t)r0g * N + nc) = make_float2(v00, v01);
                *(float2*)(Cf + (size_t)r1g * N + nc) = make_float2(v10, v11);
            }
            if (Ch) {
                uint32_t h0, h1, l0, l1;
                asm("cvt.rn.bf16x2.f32 %0, %1, %2;" : "=r"(h0) : "f"(v01), "f"(v00));
                asm("cvt.rn.bf16x2.f32 %0, %1, %2;" : "=r"(h1) : "f"(v11), "f"(v10));
                float r00 = v00 - __uint_as_float(h0 << 16);
                float r01 = v01 - __uint_as_float(h0 & 0xffff0000u);
                float r10 = v10 - __uint_as_float(h1 << 16);
                float r11 = v11 - __uint_as_float(h1 & 0xffff0000u);
                asm("cvt.rn.bf16x2.f32 %0, %1, %2;" : "=r"(l0) : "f"(r01), "f"(r00));
                asm("cvt.rn.bf16x2.f32 %0, %1, %2;" : "=r"(l1) : "f"(r11), "f"(r10));
                *(uint32_t*)(Ch + (size_t)r0g * N + nc) = h0;
                *(uint32_t*)(Ch + (size_t)r1g * N + nc) = h1;
                *(uint32_t*)(Cl + (size_t)r0g * N + nc) = l0;
                *(uint32_t*)(Cl + (size_t)r1g * N + nc) = l1;
            }
        }
    }
}

// ---------------------------------------------------------------------------
// Head: out[b] = tanh(dot(a4[b], Wp) + bp)
// ---------------------------------------------------------------------------
__global__ void head_kernel(const float* __restrict__ A, const float* __restrict__ Wp,
                            const float* __restrict__ bp, float* __restrict__ out)
{
    __shared__ float wsh[256];
    int tid = threadIdx.x;
    wsh[tid] = Wp[tid];
    __syncthreads();
    int warp = tid >> 5, lane = tid & 31;
    int b = blockIdx.x * 8 + warp;
    const float* a = A + (size_t)b * 256;
    float s = 0.0f;
    #pragma unroll
    for (int i = 0; i < 8; ++i) s += a[lane + 32 * i] * wsh[lane + 32 * i];
    #pragma unroll
    for (int o = 16; o; o >>= 1) s += __shfl_xor_sync(0xffffffffu, s, o);
    if (lane == 0) out[b] = tanhf(s + bp[0]);
}

// ---------------------------------------------------------------------------
// Launch
// ---------------------------------------------------------------------------
extern "C" void kernel_launch(void* const* d_in, const int* in_sizes, int n_in,
                              void* d_out, int out_size)
{
    const float* state = (const float*)d_in[0];
    const float* W_ih  = (const float*)d_in[1];
    const float* W_hh  = (const float*)d_in[2];
    const float* b_ih  = (const float*)d_in[3];
    const float* b_hh  = (const float*)d_in[4];
    const float* W1 = (const float*)d_in[5];  const float* b1 = (const float*)d_in[6];
    const float* W2 = (const float*)d_in[7];  const float* b2 = (const float*)d_in[8];
    const float* W3 = (const float*)d_in[9];  const float* b3 = (const float*)d_in[10];
    const float* W4 = (const float*)d_in[11]; const float* b4 = (const float*)d_in[12];
    const float* Wp = (const float*)d_in[13]; const float* bp = (const float*)d_in[14];
    float* out = (float*)d_out;

    float *pWhhT, *pWihT, *pS16, *pXg, *pXcat, *pOut4;
    __nv_bfloat16 *pXh, *pXl, *pAh, *pAl, *pBh, *pBl;
    __nv_bfloat16 *pW1h, *pW1l, *pW2h, *pW2l, *pW3h, *pW3l, *pW4h, *pW4l;
    cudaGetSymbolAddress((void**)&pWhhT, g_WhhT);
    cudaGetSymbolAddress((void**)&pWihT, g_WihT);
    cudaGetSymbolAddress((void**)&pS16,  g_state16);
    cudaGetSymbolAddress((void**)&pXg,   g_xg);
    cudaGetSymbolAddress((void**)&pXcat, g_xcat);
    cudaGetSymbolAddress((void**)&pOut4, g_out4);
    cudaGetSymbolAddress((void**)&pXh,   g_xh);
    cudaGetSymbolAddress((void**)&pXl,   g_xl);
    cudaGetSymbolAddress((void**)&pAh,   g_ah);
    cudaGetSymbolAddress((void**)&pAl,   g_al);
    cudaGetSymbolAddress((void**)&pBh,   g_bh);
    cudaGetSymbolAddress((void**)&pBl,   g_bl);
    cudaGetSymbolAddress((void**)&pW1h,  g_w1h);
    cudaGetSymbolAddress((void**)&pW1l,  g_w1l);
    cudaGetSymbolAddress((void**)&pW2h,  g_w2h);
    cudaGetSymbolAddress((void**)&pW2l,  g_w2l);
    cudaGetSymbolAddress((void**)&pW3h,  g_w3h);
    cudaGetSymbolAddress((void**)&pW3l,  g_w3l);
    cudaGetSymbolAddress((void**)&pW4h,  g_w4h);
    cudaGetSymbolAddress((void**)&pW4l,  g_w4l);

    cudaFuncSetAttribute(gru_kernel, cudaFuncAttributeMaxDynamicSharedMemorySize,
                         GRU_SMEM_BYTES);
    cudaFuncSetAttribute(wm_gemm, cudaFuncAttributeMaxDynamicSharedMemorySize,
                         WMG_SMEM);

    // prep
    transpose_pad<<<(256 * 768 + 255) / 256, 256>>>(W_hh, pWhhT, 768, 256, 256);
    transpose_pad<<<(16 * 768 + 255) / 256, 256>>>(W_ih, pWihT, 768, 15, 16);
    pad_state16<<<(B_SZ * V_DIM * 16 + 255) / 256, 256>>>(state, pS16);
    split_w1<<<(1024 * 320 + 255) / 256, 256>>>(W1, pW1h, pW1l);
    split_pad<<<(1024 * 1024 + 255) / 256, 256>>>(W2, pW2h, pW2l, 1024, 1024, 1024);
    split_pad<<<(512 * 1024 + 255) / 256, 256>>>(W3, pW3h, pW3l, 512, 1024, 1024);
    split_pad<<<(256 * 512 + 255) / 256, 256>>>(W4, pW4h, pW4l, 256, 512, 512);

    // xg = state @ W_ih^T + b_ih  (fp32, K=16, N=768)
    mlp_gemm<<<dim3(6, 2560), 256>>>(pS16, pWihT, b_ih, pXg, 16, 768, 0);

    // GRU -> g_xcat [B][272]
    gru_kernel<<<B_SZ / 32, 256, GRU_SMEM_BYTES>>>(state, b_hh);

    // split xcat -> bf16 hi/lo [B][320]
    split_pad<<<(B_SZ * 320 + 255) / 256, 256>>>(pXcat, pXh, pXl, B_SZ, 272, 320);

    // tensor-core MLP (mma.sync bf16 split)
    wm_gemm<<<dim3(8, 128), 256, WMG_SMEM>>>(pXh, pXl, pW1h, pW1l, b1,
                                             pAh, pAl, nullptr, 320, 1024);
    wm_gemm<<<dim3(8, 128), 256, WMG_SMEM>>>(pAh, pAl, pW2h, pW2l, b2,
                                             pBh, pBl, nullptr, 1024, 1024);
    wm_gemm<<<dim3(4, 128), 256, WMG_SMEM>>>(pBh, pBl, pW3h, pW3l, b3,
                                             pAh, pAl, nullptr, 1024, 512);
    wm_gemm<<<dim3(2, 128), 256, WMG_SMEM>>>(pAh, pAl, pW4h, pW4l, b4,
                                             nullptr, nullptr, pOut4, 512, 256);

    // head
    head_kernel<<<B_SZ / 8, 256>>>(pOut4, Wp, bp, out);
}

// round 13
// speedup vs baseline: 3.0135x; 1.0275x over previous
#include <cuda_runtime.h>
#include <cuda_bf16.h>
#include <cstdint>

typedef unsigned long long ull;

#define B_SZ  16384
#define V_DIM 20
#define F_DIM 15

// ---------------------------------------------------------------------------
// f32x2 packed math helpers (fp32 GRU path)
// ---------------------------------------------------------------------------
__device__ __forceinline__ ull pk2(float a) {
    ull r; asm("mov.b64 %0, {%1, %1};" : "=l"(r) : "f"(a)); return r;
}
__device__ __forceinline__ void ffma2(ull &d, ull a, ull b) {
    asm("fma.rn.f32x2 %0, %1, %2, %0;" : "+l"(d) : "l"(a), "l"(b));
}
__device__ __forceinline__ float2 upk(ull v) {
    float2 f; asm("mov.b64 {%0, %1}, %2;" : "=f"(f.x), "=f"(f.y) : "l"(v)); return f;
}
__device__ __forceinline__ float tanhfast(float x) {
    float y; asm("tanh.approx.f32 %0, %1;" : "=f"(y) : "f"(x)); return y;
}
// sigmoid with 1 MUFU instead of 2: sigma(x) = 0.5 + 0.5*tanh(x/2)
__device__ __forceinline__ float sigmfast(float x) {
    return fmaf(tanhfast(0.5f * x), 0.5f, 0.5f);
}

// ---------------------------------------------------------------------------
// mma.sync + cp.async helpers (sm_80+ PTX: legal on compute_103)
// ---------------------------------------------------------------------------
__device__ __forceinline__ uint32_t smem_u32(const void* p) {
    uint32_t a;
    asm("{ .reg .u64 t; cvta.to.shared.u64 t, %1; cvt.u32.u64 %0, t; }"
        : "=r"(a) : "l"(p));
    return a;
}
__device__ __forceinline__ void ldm4(uint32_t* r, uint32_t addr) {
    asm volatile("ldmatrix.sync.aligned.m8n8.x4.shared.b16 {%0,%1,%2,%3}, [%4];"
                 : "=r"(r[0]), "=r"(r[1]), "=r"(r[2]), "=r"(r[3]) : "r"(addr));
}
__device__ __forceinline__ void mma16816(float* c, const uint32_t* a,
                                         uint32_t b0, uint32_t b1) {
    asm volatile(
        "mma.sync.aligned.m16n8k16.row.col.f32.bf16.bf16.f32 "
        "{%0,%1,%2,%3}, {%4,%5,%6,%7}, {%8,%9}, {%0,%1,%2,%3};"
        : "+f"(c[0]), "+f"(c[1]), "+f"(c[2]), "+f"(c[3])
        : "r"(a[0]), "r"(a[1]), "r"(a[2]), "r"(a[3]), "r"(b0), "r"(b1));
}
__device__ __forceinline__ void cpa16(uint32_t dst, const void* src) {
    asm volatile("cp.async.cg.shared.global [%0], [%1], 16;"
                 :: "r"(dst), "l"(src));
}
#define CPA_COMMIT() asm volatile("cp.async.commit_group;" ::: "memory")
#define CPA_WAIT(n)  asm volatile("cp.async.wait_group %0;" :: "n"(n) : "memory")

// ---------------------------------------------------------------------------
// Device-global scratch
// ---------------------------------------------------------------------------
__device__ float g_WhhT[256 * 768];
__device__ float g_WihT[16 * 768];
__device__ float g_state16[(size_t)B_SZ * V_DIM * 16];
__device__ float g_xg[(size_t)B_SZ * V_DIM * 768];
__device__ float g_xcat[(size_t)B_SZ * 272];
__device__ float g_out4[(size_t)B_SZ * 256];

// bf16 split buffers (16B-aligned for uint4 / cp.async access)
__device__ __align__(16) __nv_bfloat16 g_xh[(size_t)B_SZ * 320];
__device__ __align__(16) __nv_bfloat16 g_xl[(size_t)B_SZ * 320];
__device__ __align__(16) __nv_bfloat16 g_ah[(size_t)B_SZ * 1024];
__device__ __align__(16) __nv_bfloat16 g_al[(size_t)B_SZ * 1024];
__device__ __align__(16) __nv_bfloat16 g_bh[(size_t)B_SZ * 1024];
__device__ __align__(16) __nv_bfloat16 g_bl[(size_t)B_SZ * 1024];
__device__ __align__(16) __nv_bfloat16 g_w1h[1024 * 320];
__device__ __align__(16) __nv_bfloat16 g_w1l[1024 * 320];
__device__ __align__(16) __nv_bfloat16 g_w2h[1024 * 1024];
__device__ __align__(16) __nv_bfloat16 g_w2l[1024 * 1024];
__device__ __align__(16) __nv_bfloat16 g_w3h[512 * 1024];
__device__ __align__(16) __nv_bfloat16 g_w3l[512 * 1024];
__device__ __align__(16) __nv_bfloat16 g_w4h[256 * 512];
__device__ __align__(16) __nv_bfloat16 g_w4l[256 * 512];

// ---------------------------------------------------------------------------
// Prep kernels
// ---------------------------------------------------------------------------
__global__ void transpose_pad(const float* __restrict__ in, float* __restrict__ out,
                              int N, int K, int Kp)
{
    int idx = blockIdx.x * 256 + threadIdx.x;
    if (idx >= Kp * N) return;
    int k = idx / N, n = idx - k * N;
    out[idx] = (k < K) ? in[n * K + k] : 0.0f;
}

__global__ void pad_state16(const float* __restrict__ s, float* __restrict__ o)
{
    int idx = blockIdx.x * 256 + threadIdx.x;
    if (idx >= B_SZ * V_DIM * 16) return;
    int r = idx >> 4, c = idx & 15;
    o[idx] = (c < F_DIM) ? s[r * F_DIM + c] : 0.0f;
}

// generic bf16 hi/lo split with K padding: in [N][K] -> out [N][Kp]
__global__ void split_pad(const float* __restrict__ in,
                          __nv_bfloat16* __restrict__ hi, __nv_bfloat16* __restrict__ lo,
                          int N, int K, int Kp)
{
    int idx = blockIdx.x * 256 + threadIdx.x;
    if (idx >= N * Kp) return;
    int n = idx / Kp, k = idx - n * Kp;
    float v = (k < K) ? in[(size_t)n * K + k] : 0.0f;
    __nv_bfloat16 h = __float2bfloat16(v);
    hi[idx] = h;
    lo[idx] = __float2bfloat16(v - __bfloat162float(h));
}

// W1 split with column permutation matching xcat = [h(256)|feat(15)|pad]
__global__ void split_w1(const float* __restrict__ W1,
                         __nv_bfloat16* __restrict__ hi, __nv_bfloat16* __restrict__ lo)
{
    int idx = blockIdx.x * 256 + threadIdx.x;
    if (idx >= 1024 * 320) return;
    int n = idx / 320, k = idx - n * 320;
    float v = 0.0f;
    if (k < 256)      v = W1[n * 271 + 15 + k];
    else if (k < 271) v = W1[n * 271 + (k - 256)];
    __nv_bfloat16 h = __float2bfloat16(v);
    hi[idx] = h;
    lo[idx] = __float2bfloat16(v - __bfloat162float(h));
}

// ---------------------------------------------------------------------------
// GRU kernel (R9 structure; activations now 3 MUFU/element instead of 5)
// ---------------------------------------------------------------------------
#define ASTRIDE 36
#define GRU_SMEM_FLOATS (2 * 16 * 768 + 256 * ASTRIDE + 768)
#define GRU_SMEM_BYTES  (GRU_SMEM_FLOATS * 4)

__global__ __launch_bounds__(256, 1)
void gru_kernel(const float* __restrict__ state, const float* __restrict__ b_hh)
{
    extern __shared__ __align__(16) float sm[];
    float* W_s = sm;
    float* A_s = sm + 2 * 16 * 768;
    float* bb  = A_s + 256 * ASTRIDE;

    const int tid  = threadIdx.x;
    const int w    = tid >> 5, lane = tid & 31;
    const int cg   = w & 1, rg = w >> 1;
    const int r0   = rg * 8;
    const int hcol = cg * 128 + lane * 4;
    const int b0   = blockIdx.x * 32;

    for (int i = tid; i < 256 * ASTRIDE; i += 256) A_s[i] = 0.0f;
    for (int i = tid; i < 768; i += 256) bb[i] = b_hh[i];

    #pragma unroll
    for (int j = 0; j < 12; ++j) {
        int f = (tid + j * 256) * 4;
        *(float4*)(W_s + f) = *(const float4*)(g_WhhT + f);
    }
    __syncthreads();

    ull acc[3][8][2];
    #pragma unroll
    for (int g = 0; g < 3; ++g)
        #pragma unroll
        for (int i = 0; i < 8; ++i) { acc[g][i][0] = 0ull; acc[g][i][1] = 0ull; }

    int buf = 0, nxt = 1;
    for (int t = 0; t < V_DIM; ++t) {
        for (int kt = 0; kt < 16; ++kt) {
            {
                const float* src = g_WhhT + nxt * (16 * 768);
                float* dst = W_s + (buf ^ 1) * 12288;
                #pragma unroll
                for (int j = 0; j < 12; ++j) {
                    int f = (tid + j * 256) * 4;
                    *(float4*)(dst + f) = *(const float4*)(src + f);
                }
            }
            const float* Wb = W_s + buf * 12288;
            #pragma unroll
            for (int kk = 0; kk < 16; ++kk) {
                const int k = kt * 16 + kk;
                float4 a0 = *(const float4*)(A_s + k * ASTRIDE + r0);
                float4 a1 = *(const float4*)(A_s + k * ASTRIDE + r0 + 4);
                ull pa[8];
                pa[0] = pk2(a0.x); pa[1] = pk2(a0.y); pa[2] = pk2(a0.z); pa[3] = pk2(a0.w);
                pa[4] = pk2(a1.x); pa[5] = pk2(a1.y); pa[6] = pk2(a1.z); pa[7] = pk2(a1.w);
                #pragma unroll
                for (int g = 0; g < 3; ++g) {
                    ulonglong2 wv = *(const ulonglong2*)(Wb + kk * 768 + g * 256 + hcol);
                    #pragma unroll
                    for (int i = 0; i < 8; ++i) {
                        ffma2(acc[g][i][0], pa[i], wv.x);
                        ffma2(acc[g][i][1], pa[i], wv.y);
                    }
                }
            }
            __syncthreads();
            buf ^= 1;
            nxt = (nxt + 1) & 15;
        }

        float4 bR = *(const float4*)(bb + 0 * 256 + hcol);
        float4 bZ = *(const float4*)(bb + 1 * 256 + hcol);
        float4 bN = *(const float4*)(bb + 2 * 256 + hcol);
        #pragma unroll
        for (int i = 0; i < 8; ++i) {
            size_t xrow = ((size_t)(b0 + r0 + i) * V_DIM + t) * 768;
            float4 xr = *(const float4*)(g_xg + xrow + 0 * 256 + hcol);
            float4 xz = *(const float4*)(g_xg + xrow + 1 * 256 + hcol);
            float4 xn = *(const float4*)(g_xg + xrow + 2 * 256 + hcol);
            float2 ar0 = upk(acc[0][i][0]), ar1 = upk(acc[0][i][1]);
            float2 az0 = upk(acc[1][i][0]), az1 = upk(acc[1][i][1]);
            float2 an0 = upk(acc[2][i][0]), an1 = upk(acc[2][i][1]);
            float rr[4], zz[4], nn[4];
            rr[0] = sigmfast(xr.x + ar0.x + bR.x);
            rr[1] = sigmfast(xr.y + ar0.y + bR.y);
            rr[2] = sigmfast(xr.z + ar1.x + bR.z);
            rr[3] = sigmfast(xr.w + ar1.y + bR.w);
            zz[0] = sigmfast(xz.x + az0.x + bZ.x);
            zz[1] = sigmfast(xz.y + az0.y + bZ.y);
            zz[2] = sigmfast(xz.z + az1.x + bZ.z);
            zz[3] = sigmfast(xz.w + az1.y + bZ.w);
            nn[0] = tanhfast(xn.x + rr[0] * (an0.x + bN.x));
            nn[1] = tanhfast(xn.y + rr[1] * (an0.y + bN.y));
            nn[2] = tanhfast(xn.z + rr[2] * (an1.x + bN.z));
            nn[3] = tanhfast(xn.w + rr[3] * (an1.y + bN.w));
            #pragma unroll
            for (int c = 0; c < 4; ++c) {
                float* hp = A_s + (hcol + c) * ASTRIDE + r0 + i;
                float h = *hp;
                *hp = nn[c] + zz[c] * (h - nn[c]);
            }
        }
        #pragma unroll
        for (int g = 0; g < 3; ++g)
            #pragma unroll
            for (int i = 0; i < 8; ++i) { acc[g][i][0] = 0ull; acc[g][i][1] = 0ull; }
        __syncthreads();
    }

    #pragma unroll
    for (int i = 0; i < 8; ++i) {
        float4 v;
        v.x = A_s[(hcol + 0) * ASTRIDE + r0 + i];
        v.y = A_s[(hcol + 1) * ASTRIDE + r0 + i];
        v.z = A_s[(hcol + 2) * ASTRIDE + r0 + i];
        v.w = A_s[(hcol + 3) * ASTRIDE + r0 + i];
        *(float4*)&g_xcat[(size_t)(b0 + r0 + i) * 272 + hcol] = v;
    }
    for (int idx = tid; idx < 32 * F_DIM; idx += 256) {
        int row = idx / F_DIM, f = idx - row * F_DIM;
        g_xcat[(size_t)(b0 + row) * 272 + 256 + f] =
            state[((size_t)(b0 + row) * V_DIM) * F_DIM + f];
    }
    if (tid < 32) g_xcat[(size_t)(b0 + tid) * 272 + 271] = 0.0f;
}

// ---------------------------------------------------------------------------
// fp32 GEMM (kept for the xg precompute: K=16, N=768)
// ---------------------------------------------------------------------------
__global__ __launch_bounds__(256, 2)
void mlp_gemm(const float* __restrict__ A, const float* __restrict__ Wt,
              const float* __restrict__ bias, float* __restrict__ C,
              int K, int N, int relu)
{
    __shared__ __align__(16) float A_s[2][16 * 128];
    __shared__ __align__(16) float W_s[2][16 * 128];

    const int tid  = threadIdx.x;
    const int tx   = tid & 15, ty = tid >> 4;
    const int m0   = blockIdx.y << 7, n0 = blockIdx.x << 7;
    const int crow = ty * 8;
    const int c1   = 4 * tx, c2 = 64 + 4 * tx;

    ull acc[8][4];
    #pragma unroll
    for (int j = 0; j < 8; ++j)
        #pragma unroll
        for (int c = 0; c < 4; ++c) acc[j][c] = 0ull;

    const int ar = tid >> 1;
    const int ac = (tid & 1) * 8;
    const int wk = ty;
    const int wc = 8 * tx;

    {
        const float* sa = A + (size_t)(m0 + ar) * K + ac;
        float4 a0 = *(const float4*)sa, a1 = *(const float4*)(sa + 4);
        A_s[0][(ac+0)*128+ar]=a0.x; A_s[0][(ac+1)*128+ar]=a0.y;
        A_s[0][(ac+2)*128+ar]=a0.z; A_s[0][(ac+3)*128+ar]=a0.w;
        A_s[0][(ac+4)*128+ar]=a1.x; A_s[0][(ac+5)*128+ar]=a1.y;
        A_s[0][(ac+6)*128+ar]=a1.z; A_s[0][(ac+7)*128+ar]=a1.w;
        const float* sw = Wt + (size_t)wk * N + n0 + wc;
        *(float4*)&W_s[0][wk*128+wc]   = *(const float4*)sw;
        *(float4*)&W_s[0][wk*128+wc+4] = *(const float4*)(sw + 4);
    }
    __syncthreads();

    const int ntile = K >> 4;
    for (int tk = 0; tk < ntile; ++tk) {
        const int cb = tk & 1;
        if (tk + 1 < ntile) {
            const int nb = cb ^ 1, k0 = (tk + 1) << 4;
            const float* sa = A + (size_t)(m0 + ar) * K + k0 + ac;
            float4 a0 = *(const float4*)sa, a1 = *(const float4*)(sa + 4);
            A_s[nb][(ac+0)*128+ar]=a0.x; A_s[nb][(ac+1)*128+ar]=a0.y;
            A_s[nb][(ac+2)*128+ar]=a0.z; A_s[nb][(ac+3)*128+ar]=a0.w;
            A_s[nb][(ac+4)*128+ar]=a1.x; A_s[nb][(ac+5)*128+ar]=a1.y;
            A_s[nb][(ac+6)*128+ar]=a1.z; A_s[nb][(ac+7)*128+ar]=a1.w;
            const float* sw = Wt + (size_t)(k0 + wk) * N + n0 + wc;
            *(float4*)&W_s[nb][wk*128+wc]   = *(const float4*)sw;
            *(float4*)&W_s[nb][wk*128+wc+4] = *(const float4*)(sw + 4);
        }
        #pragma unroll
        for (int k = 0; k < 16; ++k) {
            float4 a0 = *(const float4*)&A_s[cb][k * 128 + crow];
            float4 a1 = *(const float4*)&A_s[cb][k * 128 + crow + 4];
            ulonglong2 w1 = *(const ulonglong2*)&W_s[cb][k * 128 + c1];
            ulonglong2 w2 = *(const ulonglong2*)&W_s[cb][k * 128 + c2];
            float av[8] = {a0.x, a0.y, a0.z, a0.w, a1.x, a1.y, a1.z, a1.w};
            #pragma unroll
            for (int j = 0; j < 8; ++j) {
                ull pa = pk2(av[j]);
                ffma2(acc[j][0], pa, w1.x);
                ffma2(acc[j][1], pa, w1.y);
                ffma2(acc[j][2], pa, w2.x);
                ffma2(acc[j][3], pa, w2.y);
            }
        }
        __syncthreads();
    }

    float4 bv1 = *(const float4*)(bias + n0 + c1);
    float4 bv2 = *(const float4*)(bias + n0 + c2);
    float bvf1[4] = {bv1.x, bv1.y, bv1.z, bv1.w};
    float bvf2[4] = {bv2.x, bv2.y, bv2.z, bv2.w};
    #pragma unroll
    for (int j = 0; j < 8; ++j) {
        float o1[4], o2[4];
        {
            float2 v0 = upk(acc[j][0]), v1 = upk(acc[j][1]);
            o1[0] = v0.x + bvf1[0]; o1[1] = v0.y + bvf1[1];
            o1[2] = v1.x + bvf1[2]; o1[3] = v1.y + bvf1[3];
            float2 u0 = upk(acc[j][2]), u1 = upk(acc[j][3]);
            o2[0] = u0.x + bvf2[0]; o2[1] = u0.y + bvf2[1];
            o2[2] = u1.x + bvf2[2]; o2[3] = u1.y + bvf2[3];
        }
        if (relu) {
            #pragma unroll
            for (int c = 0; c < 4; ++c) {
                o1[c] = fmaxf(o1[c], 0.0f);
                o2[c] = fmaxf(o2[c], 0.0f);
            }
        }
        float* dst = C + (size_t)(m0 + crow + j) * N + n0;
        *(float4*)(dst + c1) = make_float4(o1[0], o1[1], o1[2], o1[3]);
        *(float4*)(dst + c2) = make_float4(o2[0], o2[1], o2[2], o2[3]);
    }
}

// ---------------------------------------------------------------------------
// Warp-MMA bf16-split GEMM with cp.async pipelined staging.
// C = relu(A @ B^T + bias); A [M][Kp], B=W [N][Kp], hi/lo bf16 row-major.
// CTA 128x128, 256 threads = 8 warps (4m x 2n), warp tile 32x64.
// smem rows stride 72 bf16 (144B) -> ldmatrix conflict-free, no swizzle.
// 3 HMMA per block: Ah*Bh + Ah*Bl + Al*Bh (al*bl dropped ~2^-17).
// ---------------------------------------------------------------------------
#define WMG_TILE_E  (128 * 72)               // bf16 per operand tile
#define WMG_TILE_B  (WMG_TILE_E * 2)         // bytes = 18432
#define WMG_BUF_B   (4 * WMG_TILE_B)         // bytes = 73728
#define WMG_SMEM    (2 * WMG_BUF_B)          // 147456 bytes

__global__ __launch_bounds__(256, 1)
void wm_gemm(const __nv_bfloat16* __restrict__ Ah, const __nv_bfloat16* __restrict__ Al,
             const __nv_bfloat16* __restrict__ Bh, const __nv_bfloat16* __restrict__ Bl,
             const float* __restrict__ bias,
             __nv_bfloat16* __restrict__ Ch, __nv_bfloat16* __restrict__ Cl,
             float* __restrict__ Cf, int Kp, int N)
{
    extern __shared__ __align__(16) __nv_bfloat16 sw[];
    const int tid  = threadIdx.x;
    const int w    = tid >> 5, lane = tid & 31;
    const int wm   = w & 3, wn = w >> 2;
    const int m0   = blockIdx.y << 7, n0 = blockIdx.x << 7;
    const int m0c  = wm * 32, n0c = wn * 64;

    float acc[2][8][4];
    #pragma unroll
    for (int mb = 0; mb < 2; ++mb)
        #pragma unroll
        for (int j = 0; j < 8; ++j)
            #pragma unroll
            for (int c = 0; c < 4; ++c) acc[mb][j][c] = 0.0f;

    const uint32_t sbase = smem_u32(sw);
    const uint32_t aByte =
        ((uint32_t)(m0c + ((lane >> 3) & 1) * 8 + (lane & 7)) * 72 + (lane >> 4) * 8) * 2;
    const uint32_t bByte =
        ((uint32_t)(n0c + (lane >> 4) * 8 + (lane & 7)) * 72 + ((lane >> 3) & 1) * 8) * 2;

    // staging: thread covers 4 16B-chunks per operand tile via cp.async
    const int srow = tid >> 1;
    const int sc8  = (tid & 1) * 4;

    auto stage = [&](int t, int buf) {
        const int koff = t * 64 + sc8 * 8;
        const uint32_t dst = sbase + buf * WMG_BUF_B
                           + (uint32_t)(srow * 72 + sc8 * 8) * 2;
        const __nv_bfloat16* s0 = Ah + (size_t)(m0 + srow) * Kp + koff;
        const __nv_bfloat16* s1 = Al + (size_t)(m0 + srow) * Kp + koff;
        const __nv_bfloat16* s2 = Bh + (size_t)(n0 + srow) * Kp + koff;
        const __nv_bfloat16* s3 = Bl + (size_t)(n0 + srow) * Kp + koff;
        #pragma unroll
        for (int q = 0; q < 4; ++q) {
            cpa16(dst + q * 16,                  s0 + q * 8);
            cpa16(dst + WMG_TILE_B + q * 16,     s1 + q * 8);
            cpa16(dst + 2 * WMG_TILE_B + q * 16, s2 + q * 8);
            cpa16(dst + 3 * WMG_TILE_B + q * 16, s3 + q * 8);
        }
        CPA_COMMIT();
    };

    const int T = Kp >> 6;
    stage(0, 0);
    if (T > 1) stage(1, 1);

    for (int t = 0; t < T; ++t) {
        const int buf = t & 1;
        if (t + 1 < T) { CPA_WAIT(1); } else { CPA_WAIT(0); }
        __syncthreads();

        const uint32_t ab = sbase + buf * WMG_BUF_B;
        #pragma unroll
        for (int kk = 0; kk < 4; ++kk) {
            uint32_t a0h[4], a1h[4], a0l[4], a1l[4];
            const uint32_t ak = ab + aByte + kk * 32;
            ldm4(a0h, ak);
            ldm4(a1h, ak + 2304);                 // +16 rows (16*144B)
            ldm4(a0l, ak + WMG_TILE_B);
            ldm4(a1l, ak + WMG_TILE_B + 2304);
            #pragma unroll
            for (int jj = 0; jj < 4; ++jj) {
                uint32_t bh[4], bl[4];
                const uint32_t bk = ab + 2 * WMG_TILE_B + bByte + jj * 2304 + kk * 32;
                ldm4(bh, bk);
                ldm4(bl, bk + WMG_TILE_B);
                mma16816(acc[0][2*jj],     a0h, bh[0], bh[1]);
                mma16816(acc[0][2*jj],     a0h, bl[0], bl[1]);
                mma16816(acc[0][2*jj],     a0l, bh[0], bh[1]);
                mma16816(acc[0][2*jj + 1], a0h, bh[2], bh[3]);
                mma16816(acc[0][2*jj + 1], a0h, bl[2], bl[3]);
                mma16816(acc[0][2*jj + 1], a0l, bh[2], bh[3]);
                mma16816(acc[1][2*jj],     a1h, bh[0], bh[1]);
                mma16816(acc[1][2*jj],     a1h, bl[0], bl[1]);
                mma16816(acc[1][2*jj],     a1l, bh[0], bh[1]);
                mma16816(acc[1][2*jj + 1], a1h, bh[2], bh[3]);
                mma16816(acc[1][2*jj + 1], a1h, bl[2], bl[3]);
                mma16816(acc[1][2*jj + 1], a1l, bh[2], bh[3]);
            }
        }
        __syncthreads();   // all warps done reading buf before refill
        if (t + 2 < T) stage(t + 2, buf);
    }

    // epilogue: thread owns rows {lr, lr+8} of each m16 block, col pair lc
    const int lr = lane >> 2;
    const int lc = (lane & 3) * 2;
    #pragma unroll
    for (int mb = 0; mb < 2; ++mb) {
        const int r0g = m0 + m0c + 16 * mb + lr;
        const int r1g = r0g + 8;
        #pragma unroll
        for (int j = 0; j < 8; ++j) {
            const int nc = n0 + n0c + 8 * j + lc;
            float2 bv = *(const float2*)(bias + nc);
            float v00 = fmaxf(acc[mb][j][0] + bv.x, 0.0f);
            float v01 = fmaxf(acc[mb][j][1] + bv.y, 0.0f);
            float v10 = fmaxf(acc[mb][j][2] + bv.x, 0.0f);
            float v11 = fmaxf(acc[mb][j][3] + bv.y, 0.0f);
            if (Cf) {
                *(float2*)(Cf + (size_t)r0g * N + nc) = make_float2(v00, v01);
                *(float2*)(Cf + (size_t)r1g * N + nc) = make_float2(v10, v11);
            }
            if (Ch) {
                uint32_t h0, h1, l0, l1;
                asm("cvt.rn.bf16x2.f32 %0, %1, %2;" : "=r"(h0) : "f"(v01), "f"(v00));
                asm("cvt.rn.bf16x2.f32 %0, %1, %2;" : "=r"(h1) : "f"(v11), "f"(v10));
                float r00 = v00 - __uint_as_float(h0 << 16);
                float r01 = v01 - __uint_as_float(h0 & 0xffff0000u);
                float r10 = v10 - __uint_as_float(h1 << 16);
                float r11 = v11 - __uint_as_float(h1 & 0xffff0000u);
                asm("cvt.rn.bf16x2.f32 %0, %1, %2;" : "=r"(l0) : "f"(r01), "f"(r00));
                asm("cvt.rn.bf16x2.f32 %0, %1, %2;" : "=r"(l1) : "f"(r11), "f"(r10));
                *(uint32_t*)(Ch + (size_t)r0g * N + nc) = h0;
                *(uint32_t*)(Ch + (size_t)r1g * N + nc) = h1;
                *(uint32_t*)(Cl + (size_t)r0g * N + nc) = l0;
                *(uint32_t*)(Cl + (size_t)r1g * N + nc) = l1;
            }
        }
    }
}

// ---------------------------------------------------------------------------
// Head: out[b] = tanh(dot(a4[b], Wp) + bp)
// ---------------------------------------------------------------------------
__global__ void head_kernel(const float* __restrict__ A, const float* __restrict__ Wp,
                            const float* __restrict__ bp, float* __restrict__ out)
{
    __shared__ float wsh[256];
    int tid = threadIdx.x;
    wsh[tid] = Wp[tid];
    __syncthreads();
    int warp = tid >> 5, lane = tid & 31;
    int b = blockIdx.x * 8 + warp;
    const float* a = A + (size_t)b * 256;
    float s = 0.0f;
    #pragma unroll
    for (int i = 0; i < 8; ++i) s += a[lane + 32 * i] * wsh[lane + 32 * i];
    #pragma unroll
    for (int o = 16; o; o >>= 1) s += __shfl_xor_sync(0xffffffffu, s, o);
    if (lane == 0) out[b] = tanhf(s + bp[0]);
}

// ---------------------------------------------------------------------------
// Launch
// ---------------------------------------------------------------------------
extern "C" void kernel_launch(void* const* d_in, const int* in_sizes, int n_in,
                              void* d_out, int out_size)
{
    const float* state = (const float*)d_in[0];
    const float* W_ih  = (const float*)d_in[1];
    const float* W_hh  = (const float*)d_in[2];
    const float* b_ih  = (const float*)d_in[3];
    const float* b_hh  = (const float*)d_in[4];
    const float* W1 = (const float*)d_in[5];  const float* b1 = (const float*)d_in[6];
    const float* W2 = (const float*)d_in[7];  const float* b2 = (const float*)d_in[8];
    const float* W3 = (const float*)d_in[9];  const float* b3 = (const float*)d_in[10];
    const float* W4 = (const float*)d_in[11]; const float* b4 = (const float*)d_in[12];
    const float* Wp = (const float*)d_in[13]; const float* bp = (const float*)d_in[14];
    float* out = (float*)d_out;

    float *pWhhT, *pWihT, *pS16, *pXg, *pXcat, *pOut4;
    __nv_bfloat16 *pXh, *pXl, *pAh, *pAl, *pBh, *pBl;
    __nv_bfloat16 *pW1h, *pW1l, *pW2h, *pW2l, *pW3h, *pW3l, *pW4h, *pW4l;
    cudaGetSymbolAddress((void**)&pWhhT, g_WhhT);
    cudaGetSymbolAddress((void**)&pWihT, g_WihT);
    cudaGetSymbolAddress((void**)&pS16,  g_state16);
    cudaGetSymbolAddress((void**)&pXg,   g_xg);
    cudaGetSymbolAddress((void**)&pXcat, g_xcat);
    cudaGetSymbolAddress((void**)&pOut4, g_out4);
    cudaGetSymbolAddress((void**)&pXh,   g_xh);
    cudaGetSymbolAddress((void**)&pXl,   g_xl);
    cudaGetSymbolAddress((void**)&pAh,   g_ah);
    cudaGetSymbolAddress((void**)&pAl,   g_al);
    cudaGetSymbolAddress((void**)&pBh,   g_bh);
    cudaGetSymbolAddress((void**)&pBl,   g_bl);
    cudaGetSymbolAddress((void**)&pW1h,  g_w1h);
    cudaGetSymbolAddress((void**)&pW1l,  g_w1l);
    cudaGetSymbolAddress((void**)&pW2h,  g_w2h);
    cudaGetSymbolAddress((void**)&pW2l,  g_w2l);
    cudaGetSymbolAddress((void**)&pW3h,  g_w3h);
    cudaGetSymbolAddress((void**)&pW3l,  g_w3l);
    cudaGetSymbolAddress((void**)&pW4h,  g_w4h);
    cudaGetSymbolAddress((void**)&pW4l,  g_w4l);

    cudaFuncSetAttribute(gru_kernel, cudaFuncAttributeMaxDynamicSharedMemorySize,
                         GRU_SMEM_BYTES);
    cudaFuncSetAttribute(wm_gemm, cudaFuncAttributeMaxDynamicSharedMemorySize,
                         WMG_SMEM);

    // prep
    transpose_pad<<<(256 * 768 + 255) / 256, 256>>>(W_hh, pWhhT, 768, 256, 256);
    transpose_pad<<<(16 * 768 + 255) / 256, 256>>>(W_ih, pWihT, 768, 15, 16);
    pad_state16<<<(B_SZ * V_DIM * 16 + 255) / 256, 256>>>(state, pS16);
    split_w1<<<(1024 * 320 + 255) / 256, 256>>>(W1, pW1h, pW1l);
    split_pad<<<(1024 * 1024 + 255) / 256, 256>>>(W2, pW2h, pW2l, 1024, 1024, 1024);
    split_pad<<<(512 * 1024 + 255) / 256, 256>>>(W3, pW3h, pW3l, 512, 1024, 1024);
    split_pad<<<(256 * 512 + 255) / 256, 256>>>(W4, pW4h, pW4l, 256, 512, 512);

    // xg = state @ W_ih^T + b_ih  (fp32, K=16, N=768)
    mlp_gemm<<<dim3(6, 2560), 256>>>(pS16, pWihT, b_ih, pXg, 16, 768, 0);

    // GRU -> g_xcat [B][272]
    gru_kernel<<<B_SZ / 32, 256, GRU_SMEM_BYTES>>>(state, b_hh);

    // split xcat -> bf16 hi/lo [B][320]
    split_pad<<<(B_SZ * 320 + 255) / 256, 256>>>(pXcat, pXh, pXl, B_SZ, 272, 320);

    // tensor-core MLP (mma.sync bf16 split, cp.async pipelined)
    wm_gemm<<<dim3(8, 128), 256, WMG_SMEM>>>(pXh, pXl, pW1h, pW1l, b1,
                                             pAh, pAl, nullptr, 320, 1024);
    wm_gemm<<<dim3(8, 128), 256, WMG_SMEM>>>(pAh, pAl, pW2h, pW2l, b2,
                                             pBh, pBl, nullptr, 1024, 1024);
    wm_gemm<<<dim3(4, 128), 256, WMG_SMEM>>>(pBh, pBl, pW3h, pW3l, b3,
                                             pAh, pAl, nullptr, 1024, 512);
    wm_gemm<<<dim3(2, 128), 256, WMG_SMEM>>>(pAh, pAl, pW4h, pW4l, b4,
                                             nullptr, nullptr, pOut4, 512, 256);

    // head
    head_kernel<<<B_SZ / 8, 256>>>(pOut4, Wp, bp, out);
}